// round 3
// baseline (speedup 1.0000x reference)
#include <cuda_runtime.h>
#include <math.h>

// ---------------- problem constants ----------------
#define DIMC   192
#define HW     56
#define WSZ    7
#define SHIFT  3
#define NHEADS 6
#define HD     32
#define HIDDEN 768
#define BATCH  32
#define NTOK   (HW*HW)          // 3136
#define NWIN   64               // windows per image (8x8)
#define NBLKS  (BATCH*NWIN)     // 2048
#define NTOKW  49               // tokens per window

// ---------------- scratch (device global; no allocations) ----------------
__device__ float g_xattn[(size_t)BATCH * NTOK * DIMC];

// ---------------- helpers ----------------
__device__ __forceinline__ float warp_sum(float v){
#pragma unroll
    for (int o = 16; o; o >>= 1) v += __shfl_xor_sync(0xffffffffu, v, o);
    return v;
}
__device__ __forceinline__ float warp_max(float v){
#pragma unroll
    for (int o = 16; o; o >>= 1) v = fmaxf(v, __shfl_xor_sync(0xffffffffu, v, o));
    return v;
}
__device__ __forceinline__ float gelu_exact(float x){
    return 0.5f * x * (1.0f + erff(x * 0.70710678118654752440f));
}

// =====================================================================
// Kernel 1: shifted-window attention, one CTA per window.
//   gather(roll -3) -> LN1 -> per-head QKV -> softmax(QK^T)V -> proj
//   -> scatter(roll +3) into g_xattn
// =====================================================================
#define AT_THREADS 192
#define SX_STRIDE  196
#define QV_STRIDE  33
#define SSTRIDE    56
#define ATT_SMEM_FLOATS (50*SX_STRIDE + 49*SX_STRIDE + 3*49*QV_STRIDE + 49*SSTRIDE)
#define ATT_SMEM_BYTES  (ATT_SMEM_FLOATS * 4)

__global__ __launch_bounds__(AT_THREADS)
void attn_kernel(const float* __restrict__ x,
                 const float* __restrict__ qkv_w, const float* __restrict__ qkv_b,
                 const float* __restrict__ proj_w, const float* __restrict__ proj_b,
                 const float* __restrict__ g1, const float* __restrict__ be1)
{
    extern __shared__ float sm[];
    float* s_x = sm;                        // [50][196]  (row 49 = scratch pad)
    float* s_o = s_x + 50*SX_STRIDE;        // [49][196]
    float* s_q = s_o + 49*SX_STRIDE;        // [49][33]
    float* s_k = s_q + 49*QV_STRIDE;        // [49][33]
    float* s_v = s_k + 49*QV_STRIDE;        // [49][33]
    float* s_S = s_v + 49*QV_STRIDE;        // [49][56]

    const int t   = threadIdx.x;
    const int blk = blockIdx.x;
    const int b   = blk >> 6;
    const int win = blk & 63;
    const int wr  = win >> 3, wc = win & 7;

    const float* xb = x + (size_t)b * NTOK * DIMC;

    // --- gather with cyclic shift (roll -3,-3) ---
    for (int idx = t; idx < NTOKW*DIMC; idx += AT_THREADS){
        int row = idx / DIMC, c = idx - row*DIMC;
        int ti = row / WSZ, tj = row - ti*WSZ;
        int sr = wr*WSZ + ti + SHIFT; if (sr >= HW) sr -= HW;
        int sc = wc*WSZ + tj + SHIFT; if (sc >= HW) sc -= HW;
        s_x[row*SX_STRIDE + c] = xb[(sr*HW + sc)*DIMC + c];
    }
    __syncthreads();

    const int wid = t >> 5, lane = t & 31;

    // --- LN1 in place ---
    for (int r = wid; r < NTOKW; r += 6){
        float s = 0.f, s2 = 0.f;
#pragma unroll
        for (int c = lane; c < DIMC; c += 32){
            float v = s_x[r*SX_STRIDE + c]; s += v; s2 += v*v;
        }
        s = warp_sum(s); s2 = warp_sum(s2);
        float mu = s * (1.0f/DIMC);
        float rs = rsqrtf(s2*(1.0f/DIMC) - mu*mu + 1e-5f);
#pragma unroll
        for (int c = lane; c < DIMC; c += 32){
            float v = s_x[r*SX_STRIDE + c];
            s_x[r*SX_STRIDE + c] = (v - mu)*rs*g1[c] + be1[c];
        }
    }
    __syncthreads();

    // --- per-head attention ---
    for (int h = 0; h < NHEADS; h++){
        // QKV slice for this head: [49,192] @ [192,96]
        {
            const int col96 = t % 96;
            const int rg    = t / 96;           // 0 or 1
            const int which = col96 >> 5;       // 0=q 1=k 2=v
            const int d     = col96 & 31;
            const int wcol  = which*DIMC + h*HD + d;
            const float* wp = qkv_w + wcol;
            float acc[25];
#pragma unroll
            for (int i = 0; i < 25; i++) acc[i] = 0.f;
            const float* xr0 = s_x + (rg*25)*SX_STRIDE;
#pragma unroll 2
            for (int k = 0; k < DIMC; k++){
                float w = wp[k*(3*DIMC)];
#pragma unroll
                for (int i = 0; i < 25; i++)
                    acc[i] += xr0[i*SX_STRIDE + k] * w;   // rg=1,i=24 hits pad row 49 (discarded)
            }
            float bias = qkv_b[wcol];
            float* dst = (which == 0) ? s_q : (which == 1) ? s_k : s_v;
            const int r0 = rg*25;
#pragma unroll
            for (int i = 0; i < 25; i++){
                int r = r0 + i;
                if (r < NTOKW) dst[r*QV_STRIDE + d] = acc[i] + bias;
            }
        }
        __syncthreads();

        // S = scale * q k^T
        for (int idx = t; idx < NTOKW*NTOKW; idx += AT_THREADS){
            int i = idx / NTOKW, j = idx - i*NTOKW;
            const float* qi = s_q + i*QV_STRIDE;
            const float* kj = s_k + j*QV_STRIDE;
            float s = 0.f;
#pragma unroll
            for (int d2 = 0; d2 < HD; d2++) s += qi[d2]*kj[d2];
            s_S[i*SSTRIDE + j] = s * 0.17677669529663688110f;  // 1/sqrt(32)
        }
        __syncthreads();

        // row softmax
        for (int r = wid; r < NTOKW; r += 6){
            float v0 = (lane      < NTOKW) ? s_S[r*SSTRIDE + lane     ] : -1e30f;
            float v1 = (lane + 32 < NTOKW) ? s_S[r*SSTRIDE + lane + 32] : -1e30f;
            float m  = warp_max(fmaxf(v0, v1));
            float e0 = (lane      < NTOKW) ? __expf(v0 - m) : 0.f;
            float e1 = (lane + 32 < NTOKW) ? __expf(v1 - m) : 0.f;
            float inv = 1.0f / warp_sum(e0 + e1);
            if (lane      < NTOKW) s_S[r*SSTRIDE + lane     ] = e0 * inv;
            if (lane + 32 < NTOKW) s_S[r*SSTRIDE + lane + 32] = e1 * inv;
        }
        __syncthreads();

        // O = P @ v  -> columns [h*32, h*32+32) of s_o
        for (int idx = t; idx < NTOKW*HD; idx += AT_THREADS){
            int i = idx >> 5, d2 = idx & 31;
            const float* pi = s_S + i*SSTRIDE;
            const float* vd = s_v + d2;
            float s = 0.f;
#pragma unroll
            for (int j = 0; j < NTOKW; j++) s += pi[j] * vd[j*QV_STRIDE];
            s_o[i*SX_STRIDE + h*HD + d2] = s;
        }
        __syncthreads();
    }

    // --- proj [49,192]@[192,192] + scatter (roll +3,+3) ---
    {
        const int col = t;   // 192 threads == 192 cols
        float acc[NTOKW];
#pragma unroll
        for (int i = 0; i < NTOKW; i++) acc[i] = 0.f;
        const float* wp = proj_w + col;
#pragma unroll 2
        for (int k = 0; k < DIMC; k++){
            float w = wp[k*DIMC];
#pragma unroll
            for (int i = 0; i < NTOKW; i++)
                acc[i] += s_o[i*SX_STRIDE + k] * w;
        }
        float bias = proj_b[col];
        float* ob = g_xattn + (size_t)b * NTOK * DIMC;
#pragma unroll
        for (int i = 0; i < NTOKW; i++){
            int ti = i / WSZ, tj = i - ti*WSZ;
            int sr = wr*WSZ + ti + SHIFT; if (sr >= HW) sr -= HW;
            int sc = wc*WSZ + tj + SHIFT; if (sc >= HW) sc -= HW;
            ob[(sr*HW + sc)*DIMC + col] = acc[i] + bias;
        }
    }
}

// =====================================================================
// Kernel 2: fused MLP with residual.  out = x + gelu(LN2(x)@w1+b1)@w2 + b2
// 64 tokens/CTA, hidden processed in 12 chunks of 64 (never hits HBM).
// =====================================================================
#define ML_THREADS 256
#define TM 64
#define TH 64
#define XN_STRIDE 196
#define H_STRIDE  68
#define W2_STRIDE 196
#define MLP_SMEM_FLOATS (TM*XN_STRIDE + DIMC*TH + TM*H_STRIDE + TH*W2_STRIDE)
#define MLP_SMEM_BYTES  (MLP_SMEM_FLOATS * 4)

__global__ __launch_bounds__(ML_THREADS)
void mlp_kernel(const float* __restrict__ g2, const float* __restrict__ be2,
                const float* __restrict__ w1, const float* __restrict__ b1,
                const float* __restrict__ w2, const float* __restrict__ b2,
                float* __restrict__ out)
{
    extern __shared__ float sm[];
    float* s_xn = sm;                       // [64][196]
    float* s_w1 = s_xn + TM*XN_STRIDE;      // [192][64]
    float* s_h  = s_w1 + DIMC*TH;           // [64][68]
    float* s_w2 = s_h  + TM*H_STRIDE;       // [64][196]

    const int t = threadIdx.x;
    const size_t tok0 = (size_t)blockIdx.x * TM;
    const float* xb = g_xattn + tok0 * DIMC;

    // load tile
    for (int idx = t; idx < TM*DIMC; idx += ML_THREADS){
        int r = idx / DIMC, c = idx - r*DIMC;
        s_xn[r*XN_STRIDE + c] = xb[idx];
    }
    __syncthreads();

    const int wid = t >> 5, lane = t & 31;
    // LN2 in place
    for (int r = wid; r < TM; r += 8){
        float s = 0.f, s2 = 0.f;
#pragma unroll
        for (int c = lane; c < DIMC; c += 32){
            float v = s_xn[r*XN_STRIDE + c]; s += v; s2 += v*v;
        }
        s = warp_sum(s); s2 = warp_sum(s2);
        float mu = s * (1.0f/DIMC);
        float rs = rsqrtf(s2*(1.0f/DIMC) - mu*mu + 1e-5f);
#pragma unroll
        for (int c = lane; c < DIMC; c += 32){
            float v = s_xn[r*XN_STRIDE + c];
            s_xn[r*XN_STRIDE + c] = (v - mu)*rs*g2[c] + be2[c];
        }
    }

    const int tr = t >> 4, tc = t & 15;
    const int r1 = tr*4, c1 = tc*4;     // gemm1 micro-tile (4x4 of [64][64])
    const int ro = tr*4, co = tc*12;    // out micro-tile   (4x12 of [64][192])

    float acc[4][12];
#pragma unroll
    for (int i = 0; i < 4; i++)
#pragma unroll
        for (int j = 0; j < 12; j++) acc[i][j] = 0.f;

    for (int hc = 0; hc < HIDDEN; hc += TH){
        __syncthreads();   // prior chunk readers done (also orders LN writes on 1st iter)

        // stage weight chunks
        for (int idx = t; idx < DIMC*TH; idx += ML_THREADS){
            int k = idx >> 6, cc = idx & 63;
            s_w1[idx] = w1[(size_t)k*HIDDEN + hc + cc];
        }
        for (int idx = t; idx < TH*DIMC; idx += ML_THREADS){
            int k = idx / DIMC, c = idx - k*DIMC;
            s_w2[k*W2_STRIDE + c] = w2[(size_t)(hc + k)*DIMC + c];
        }
        __syncthreads();

        // GEMM1: h_tile[64][64] = xn @ w1_chunk
        float ha[4][4];
#pragma unroll
        for (int i = 0; i < 4; i++)
#pragma unroll
            for (int j = 0; j < 4; j++) ha[i][j] = 0.f;

#pragma unroll 2
        for (int k = 0; k < DIMC; k++){
            float4 bv = *(const float4*)(s_w1 + k*TH + c1);
            float bb[4] = {bv.x, bv.y, bv.z, bv.w};
            float aa[4];
#pragma unroll
            for (int i = 0; i < 4; i++) aa[i] = s_xn[(r1+i)*XN_STRIDE + k];
#pragma unroll
            for (int i = 0; i < 4; i++)
#pragma unroll
                for (int j = 0; j < 4; j++) ha[i][j] += aa[i]*bb[j];
        }
        // bias + exact GELU -> s_h
#pragma unroll
        for (int i = 0; i < 4; i++)
#pragma unroll
            for (int j = 0; j < 4; j++){
                float hv = ha[i][j] + b1[hc + c1 + j];
                s_h[(r1+i)*H_STRIDE + c1 + j] = gelu_exact(hv);
            }
        __syncthreads();

        // GEMM2: acc += h_tile @ w2_chunk
#pragma unroll 2
        for (int k = 0; k < TH; k++){
            float aa[4];
#pragma unroll
            for (int i = 0; i < 4; i++) aa[i] = s_h[(ro+i)*H_STRIDE + k];
            const float* wrow = s_w2 + k*W2_STRIDE + co;
            float4 b0 = *(const float4*)(wrow);
            float4 b1v = *(const float4*)(wrow + 4);
            float4 b2v = *(const float4*)(wrow + 8);
            float bb[12] = {b0.x,b0.y,b0.z,b0.w, b1v.x,b1v.y,b1v.z,b1v.w,
                            b2v.x,b2v.y,b2v.z,b2v.w};
#pragma unroll
            for (int i = 0; i < 4; i++)
#pragma unroll
                for (int j = 0; j < 12; j++) acc[i][j] += aa[i]*bb[j];
        }
    }
    __syncthreads();

    // stage raw acc to smem for a coalesced epilogue
#pragma unroll
    for (int i = 0; i < 4; i++)
#pragma unroll
        for (int j = 0; j < 12; j++)
            s_xn[(ro+i)*XN_STRIDE + co + j] = acc[i][j];
    __syncthreads();

    float* ob = out + tok0 * DIMC;
    for (int idx = t; idx < TM*DIMC; idx += ML_THREADS){
        int r = idx / DIMC, c = idx - r*DIMC;
        ob[idx] = s_xn[r*XN_STRIDE + c] + b2[c] + xb[idx];  // residual + bias
    }
}

// =====================================================================
// launch
// =====================================================================
extern "C" void kernel_launch(void* const* d_in, const int* in_sizes, int n_in,
                              void* d_out, int out_size)
{
    (void)in_sizes; (void)n_in; (void)out_size;
    const float* x      = (const float*)d_in[0];
    const float* qkv_w  = (const float*)d_in[1];
    const float* qkv_b  = (const float*)d_in[2];
    const float* proj_w = (const float*)d_in[3];
    const float* proj_b = (const float*)d_in[4];
    const float* g1     = (const float*)d_in[5];
    const float* be1    = (const float*)d_in[6];
    const float* g2     = (const float*)d_in[7];
    const float* be2    = (const float*)d_in[8];
    const float* w1     = (const float*)d_in[9];
    const float* b1     = (const float*)d_in[10];
    const float* w2     = (const float*)d_in[11];
    const float* b2     = (const float*)d_in[12];
    float* out = (float*)d_out;

    cudaFuncSetAttribute(attn_kernel, cudaFuncAttributeMaxDynamicSharedMemorySize, ATT_SMEM_BYTES);
    cudaFuncSetAttribute(mlp_kernel,  cudaFuncAttributeMaxDynamicSharedMemorySize, MLP_SMEM_BYTES);

    attn_kernel<<<NBLKS, AT_THREADS, ATT_SMEM_BYTES>>>(x, qkv_w, qkv_b, proj_w, proj_b, g1, be1);
    mlp_kernel<<<(BATCH*NTOK)/TM, ML_THREADS, MLP_SMEM_BYTES>>>(g2, be2, w1, b1, w2, b2, out);
}

// round 4
// speedup vs baseline: 1.2440x; 1.2440x over previous
#include <cuda_runtime.h>
#include <math.h>
#include <mma.h>

using namespace nvcuda;

// ---------------- problem constants ----------------
#define DIMC   192
#define HW     56
#define WSZ    7
#define SHIFT  3
#define NHEADS 6
#define HD     32
#define HIDDEN 768
#define BATCH  32
#define NTOK   (HW*HW)          // 3136
#define NBLKS  (BATCH*64)       // 2048 windows
#define NTOKW  49

// ---------------- scratch ----------------
__device__ float g_xattn[(size_t)BATCH * NTOK * DIMC];

// ---------------- helpers ----------------
__device__ __forceinline__ float warp_sum(float v){
#pragma unroll
    for (int o = 16; o; o >>= 1) v += __shfl_xor_sync(0xffffffffu, v, o);
    return v;
}
__device__ __forceinline__ float warp_max(float v){
#pragma unroll
    for (int o = 16; o; o >>= 1) v = fmaxf(v, __shfl_xor_sync(0xffffffffu, v, o));
    return v;
}
__device__ __forceinline__ float gelu_exact(float x){
    return 0.5f * x * (1.0f + erff(x * 0.70710678118654752440f));
}

// ---------------- wmma tf32 helpers ----------------
typedef wmma::fragment<wmma::matrix_a, 16, 16, 8, wmma::precision::tf32, wmma::row_major> FragA;
typedef wmma::fragment<wmma::matrix_b, 16, 16, 8, wmma::precision::tf32, wmma::row_major> FragB;
typedef wmma::fragment<wmma::accumulator, 16, 16, 8, float> FragC;

__device__ __forceinline__ void load_a_tf32(FragA& f, const float* p, int ld){
    wmma::load_matrix_sync(f, p, ld);
#pragma unroll
    for (int i = 0; i < f.num_elements; i++) f.x[i] = wmma::__float_to_tf32(f.x[i]);
}
__device__ __forceinline__ void load_b_tf32(FragB& f, const float* p, int ld){
    wmma::load_matrix_sync(f, p, ld);
#pragma unroll
    for (int i = 0; i < f.num_elements; i++) f.x[i] = wmma::__float_to_tf32(f.x[i]);
}

// =====================================================================
// Kernel 1: shifted-window attention, one CTA per window. TF32 wmma for
// QKV + proj GEMMs; SIMT fp32 for S / softmax / PV.
// =====================================================================
#define AT_THREADS 384
#define SX  200     // s_x / s_o / output stride
#define QVS 40      // q/k/v stride
#define SBQ 104     // qkv B-stage stride
#define SBP 200     // proj B-stage stride
#define SST 56

// smem float offsets
#define OFF_X  0
#define OFF_O  (OFF_X + 64*SX)              // 12800
#define OFF_Q  (OFF_O + 64*SX)              // 25600
#define OFF_K  (OFF_Q + 64*QVS)             // 28160
#define OFF_V  (OFF_K + 64*QVS)             // 30720
#define OFF_S  (OFF_V + 64*QVS)             // 33280
#define OFF_B  (OFF_S + 64*SST)             // 36864
#define ATT_SMEM_FLOATS (OFF_B + 32*SBP)    // 43264
#define ATT_SMEM_BYTES  (ATT_SMEM_FLOATS*4) // 173056

__global__ __launch_bounds__(AT_THREADS)
void attn_kernel(const float* __restrict__ x,
                 const float* __restrict__ qkv_w, const float* __restrict__ qkv_b,
                 const float* __restrict__ proj_w, const float* __restrict__ proj_b,
                 const float* __restrict__ g1, const float* __restrict__ be1)
{
    extern __shared__ float sm[];
    float* s_x = sm + OFF_X;
    float* s_o = sm + OFF_O;
    float* s_q = sm + OFF_Q;
    float* s_k = sm + OFF_K;
    float* s_v = sm + OFF_V;
    float* s_S = sm + OFF_S;
    float* s_b = sm + OFF_B;

    const int t   = threadIdx.x;
    const int wid = t >> 5, lane = t & 31;
    const int blk = blockIdx.x;
    const int b   = blk >> 6;
    const int win = blk & 63;
    const int wr  = win >> 3, wc = win & 7;

    const float* xb = x + (size_t)b * NTOK * DIMC;

    // zero pad rows 49..63 of s_x and s_o
    for (int idx = t; idx < 15*SX; idx += AT_THREADS){
        s_x[49*SX + idx] = 0.f;
        s_o[49*SX + idx] = 0.f;
    }
    // gather with cyclic shift (roll -3,-3)
    for (int idx = t; idx < NTOKW*DIMC; idx += AT_THREADS){
        int row = idx / DIMC, c = idx - row*DIMC;
        int ti = row / WSZ, tj = row - ti*WSZ;
        int sr = wr*WSZ + ti + SHIFT; if (sr >= HW) sr -= HW;
        int sc = wc*WSZ + tj + SHIFT; if (sc >= HW) sc -= HW;
        s_x[row*SX + c] = xb[(sr*HW + sc)*DIMC + c];
    }
    __syncthreads();

    // LN1 in place (rows < 49)
    for (int r = wid; r < NTOKW; r += 12){
        float s = 0.f, s2 = 0.f;
#pragma unroll
        for (int c = lane; c < DIMC; c += 32){
            float v = s_x[r*SX + c]; s += v; s2 += v*v;
        }
        s = warp_sum(s); s2 = warp_sum(s2);
        float mu = s * (1.0f/DIMC);
        float rs = rsqrtf(s2*(1.0f/DIMC) - mu*mu + 1e-5f);
#pragma unroll
        for (int c = lane; c < DIMC; c += 32){
            float v = s_x[r*SX + c];
            s_x[r*SX + c] = (v - mu)*rs*g1[c] + be1[c];
        }
    }
    // (kc-loop top sync below orders LN before wmma reads)

    const int ti  = wid & 3;        // row tile 0..3
    const int pj  = wid >> 2;       // 0..2 : q / k / v group
    const int tj0 = 2*pj;

    for (int h = 0; h < NHEADS; h++){
        // ---- QKV slice [64,192] @ [192,96] ----
        FragC acc0, acc1;
        wmma::fill_fragment(acc0, 0.f);
        wmma::fill_fragment(acc1, 0.f);

        for (int kc = 0; kc < 6; kc++){
            __syncthreads();                 // s_b reuse + (first iter) LN order
            for (int idx = t; idx < 32*96; idx += AT_THREADS){
                int row = idx / 96, c = idx - row*96;
                int which = c >> 5, d = c & 31;
                s_b[row*SBQ + c] = qkv_w[(size_t)(kc*32 + row)*(3*DIMC) + which*DIMC + h*HD + d];
            }
            __syncthreads();
#pragma unroll
            for (int ks = 0; ks < 4; ks++){
                FragA fa; load_a_tf32(fa, s_x + ti*16*SX + kc*32 + ks*8, SX);
                FragB fb;
                load_b_tf32(fb, s_b + ks*8*SBQ + tj0*16, SBQ);
                wmma::mma_sync(acc0, fa, fb, acc0);
                load_b_tf32(fb, s_b + ks*8*SBQ + tj0*16 + 16, SBQ);
                wmma::mma_sync(acc1, fa, fb, acc1);
            }
        }
        {
            float* base = (pj == 0) ? s_q : (pj == 1) ? s_k : s_v;
            wmma::store_matrix_sync(base + ti*16*QVS + 0,  acc0, QVS, wmma::mem_row_major);
            wmma::store_matrix_sync(base + ti*16*QVS + 16, acc1, QVS, wmma::mem_row_major);
        }
        __syncthreads();

        // bias (general; zeros in this dataset)
        for (int idx = t; idx < NTOKW*96; idx += AT_THREADS){
            int row = idx / 96, c = idx - row*96;
            int which = c >> 5, d = c & 31;
            float* base = (which == 0) ? s_q : (which == 1) ? s_k : s_v;
            base[row*QVS + d] += qkv_b[which*DIMC + h*HD + d];
        }
        __syncthreads();

        // S = scale * q k^T  (SIMT)
        for (int idx = t; idx < NTOKW*NTOKW; idx += AT_THREADS){
            int i = idx / NTOKW, j = idx - i*NTOKW;
            const float* qi = s_q + i*QVS;
            const float* kj = s_k + j*QVS;
            float s = 0.f;
#pragma unroll
            for (int d2 = 0; d2 < HD; d2++) s += qi[d2]*kj[d2];
            s_S[i*SST + j] = s * 0.17677669529663688110f;
        }
        __syncthreads();

        // row softmax
        for (int r = wid; r < NTOKW; r += 12){
            float v0 = (lane      < NTOKW) ? s_S[r*SST + lane     ] : -1e30f;
            float v1 = (lane + 32 < NTOKW) ? s_S[r*SST + lane + 32] : -1e30f;
            float m  = warp_max(fmaxf(v0, v1));
            float e0 = (lane      < NTOKW) ? __expf(v0 - m) : 0.f;
            float e1 = (lane + 32 < NTOKW) ? __expf(v1 - m) : 0.f;
            float inv = 1.0f / warp_sum(e0 + e1);
            if (lane      < NTOKW) s_S[r*SST + lane     ] = e0 * inv;
            if (lane + 32 < NTOKW) s_S[r*SST + lane + 32] = e1 * inv;
        }
        __syncthreads();

        // O = P @ v -> cols [h*32, h*32+32) of s_o
        for (int idx = t; idx < NTOKW*HD; idx += AT_THREADS){
            int i = idx >> 5, d2 = idx & 31;
            const float* pi = s_S + i*SST;
            const float* vd = s_v + d2;
            float s = 0.f;
#pragma unroll
            for (int j = 0; j < NTOKW; j++) s += pi[j] * vd[j*QVS];
            s_o[i*SX + h*HD + d2] = s;
        }
        __syncthreads();
    }

    // ---- proj: [64,192] @ [192,192], wmma ----
    {
        const int c0 = wid >> 2;   // 0..2 ; warp's col tiles: c0, c0+3, c0+6, c0+9
        FragC pacc[4];
#pragma unroll
        for (int j = 0; j < 4; j++) wmma::fill_fragment(pacc[j], 0.f);

        for (int kc = 0; kc < 6; kc++){
            __syncthreads();
            for (int idx = t; idx < 32*DIMC; idx += AT_THREADS){
                int row = idx / DIMC, c = idx - row*DIMC;
                s_b[row*SBP + c] = proj_w[(size_t)(kc*32 + row)*DIMC + c];
            }
            __syncthreads();
#pragma unroll
            for (int ks = 0; ks < 4; ks++){
                FragA fa; load_a_tf32(fa, s_o + ti*16*SX + kc*32 + ks*8, SX);
#pragma unroll
                for (int j = 0; j < 4; j++){
                    FragB fb; load_b_tf32(fb, s_b + ks*8*SBP + (c0 + 3*j)*16, SBP);
                    wmma::mma_sync(pacc[j], fa, fb, pacc[j]);
                }
            }
        }
        __syncthreads();  // all mma readers of s_x long done; readers of s_o done
#pragma unroll
        for (int j = 0; j < 4; j++)
            wmma::store_matrix_sync(s_x + ti*16*SX + (c0 + 3*j)*16, pacc[j], SX, wmma::mem_row_major);
        __syncthreads();

        // scatter (roll +3,+3)
        float* ob = g_xattn + (size_t)b * NTOK * DIMC;
        for (int idx = t; idx < NTOKW*DIMC; idx += AT_THREADS){
            int row = idx / DIMC, c = idx - row*DIMC;
            int ti2 = row / WSZ, tj2 = row - ti2*WSZ;
            int sr = wr*WSZ + ti2 + SHIFT; if (sr >= HW) sr -= HW;
            int sc = wc*WSZ + tj2 + SHIFT; if (sc >= HW) sc -= HW;
            ob[(sr*HW + sc)*DIMC + c] = s_x[row*SX + c] + proj_b[c];
        }
    }
}

// =====================================================================
// Kernel 2: fused MLP (TF32 wmma). out = x + gelu(LN2(x)@w1+b1)@w2 + b2
// 64 tokens/CTA, hidden in 12 chunks of 64, hidden never hits HBM.
// =====================================================================
#define ML_THREADS 512
#define TM 64
#define TH 64
#define XNS 200
#define W1S 72
#define HS  72
#define W2S 200
#define MOFF_XN 0
#define MOFF_W1 (MOFF_XN + TM*XNS)          // 12800
#define MOFF_H  (MOFF_W1 + DIMC*W1S)        // 26624
#define MOFF_W2 (MOFF_H  + TM*HS)           // 31232
#define MLP_SMEM_FLOATS (MOFF_W2 + TH*W2S)  // 44032
#define MLP_SMEM_BYTES  (MLP_SMEM_FLOATS*4) // 176128

__global__ __launch_bounds__(ML_THREADS)
void mlp_kernel(const float* __restrict__ g2, const float* __restrict__ be2,
                const float* __restrict__ w1, const float* __restrict__ b1,
                const float* __restrict__ w2, const float* __restrict__ b2,
                float* __restrict__ out)
{
    extern __shared__ float sm[];
    float* s_xn = sm + MOFF_XN;   // [64][200]
    float* s_w1 = sm + MOFF_W1;   // [192][72] (64 cols used)
    float* s_h  = sm + MOFF_H;    // [64][72]
    float* s_w2 = sm + MOFF_W2;   // [64][200] (192 cols used)

    const int t = threadIdx.x;
    const int wid = t >> 5, lane = t & 31;
    const size_t tok0 = (size_t)blockIdx.x * TM;
    const float* xb = g_xattn + tok0 * DIMC;

    for (int idx = t; idx < TM*DIMC; idx += ML_THREADS){
        int r = idx / DIMC, c = idx - r*DIMC;
        s_xn[r*XNS + c] = xb[idx];
    }
    __syncthreads();

    // LN2 in place
    for (int r = wid; r < TM; r += 16){
        float s = 0.f, s2 = 0.f;
#pragma unroll
        for (int c = lane; c < DIMC; c += 32){
            float v = s_xn[r*XNS + c]; s += v; s2 += v*v;
        }
        s = warp_sum(s); s2 = warp_sum(s2);
        float mu = s * (1.0f/DIMC);
        float rs = rsqrtf(s2*(1.0f/DIMC) - mu*mu + 1e-5f);
#pragma unroll
        for (int c = lane; c < DIMC; c += 32){
            float v = s_xn[r*XNS + c];
            s_xn[r*XNS + c] = (v - mu)*rs*g2[c] + be2[c];
        }
    }

    // GEMM1 tiles: ti1 = wid>>2 (row), tj1 = wid&3 (col) over [4][4]
    // GEMM2 tiles: rw = wid&3 (row), cols cw, cw+4, cw+8 with cw = wid>>2
    const int ti1 = wid >> 2, tj1 = wid & 3;
    const int rw  = wid & 3,  cw  = wid >> 2;

    FragC acc2[3];
#pragma unroll
    for (int j = 0; j < 3; j++) wmma::fill_fragment(acc2[j], 0.f);

    for (int hc = 0; hc < 12; hc++){
        const int h0 = hc * TH;
        __syncthreads();   // protects s_w1/s_w2/s_h reuse; first iter orders LN

        for (int idx = t; idx < DIMC*TH; idx += ML_THREADS){
            int row = idx >> 6, c = idx & 63;
            s_w1[row*W1S + c] = w1[(size_t)row*HIDDEN + h0 + c];
        }
        for (int idx = t; idx < TH*DIMC; idx += ML_THREADS){
            int row = idx / DIMC, c = idx - row*DIMC;
            s_w2[row*W2S + c] = w2[(size_t)(h0 + row)*DIMC + c];
        }
        __syncthreads();

        // GEMM1: H[64,64] = Xn[64,192] @ W1c[192,64]
        FragC acc1;
        wmma::fill_fragment(acc1, 0.f);
#pragma unroll
        for (int ks = 0; ks < 24; ks++){
            FragA fa; load_a_tf32(fa, s_xn + ti1*16*XNS + ks*8, XNS);
            FragB fb; load_b_tf32(fb, s_w1 + ks*8*W1S + tj1*16, W1S);
            wmma::mma_sync(acc1, fa, fb, acc1);
        }
        wmma::store_matrix_sync(s_h + ti1*16*HS + tj1*16, acc1, HS, wmma::mem_row_major);
        __syncthreads();

        // bias + exact GELU
        for (int idx = t; idx < TM*TH; idx += ML_THREADS){
            int row = idx >> 6, c = idx & 63;
            float v = s_h[row*HS + c] + b1[h0 + c];
            s_h[row*HS + c] = gelu_exact(v);
        }
        __syncthreads();

        // GEMM2: acc2 += H[64,64] @ W2c[64,192]
#pragma unroll
        for (int ks = 0; ks < 8; ks++){
            FragA fa; load_a_tf32(fa, s_h + rw*16*HS + ks*8, HS);
#pragma unroll
            for (int j = 0; j < 3; j++){
                FragB fb; load_b_tf32(fb, s_w2 + ks*8*W2S + (cw + 4*j)*16, W2S);
                wmma::mma_sync(acc2[j], fa, fb, acc2[j]);
            }
        }
    }
    __syncthreads();  // all GEMM1 readers of s_xn done -> safe to overwrite
#pragma unroll
    for (int j = 0; j < 3; j++)
        wmma::store_matrix_sync(s_xn + rw*16*XNS + (cw + 4*j)*16, acc2[j], XNS, wmma::mem_row_major);
    __syncthreads();

    float* ob = out + tok0 * DIMC;
    for (int idx = t; idx < TM*DIMC; idx += ML_THREADS){
        int r = idx / DIMC, c = idx - r*DIMC;
        ob[idx] = s_xn[r*XNS + c] + b2[c] + xb[idx];   // +bias +residual
    }
}

// =====================================================================
// launch
// =====================================================================
extern "C" void kernel_launch(void* const* d_in, const int* in_sizes, int n_in,
                              void* d_out, int out_size)
{
    (void)in_sizes; (void)n_in; (void)out_size;
    const float* x      = (const float*)d_in[0];
    const float* qkv_w  = (const float*)d_in[1];
    const float* qkv_b  = (const float*)d_in[2];
    const float* proj_w = (const float*)d_in[3];
    const float* proj_b = (const float*)d_in[4];
    const float* g1     = (const float*)d_in[5];
    const float* be1    = (const float*)d_in[6];
    const float* g2     = (const float*)d_in[7];
    const float* be2    = (const float*)d_in[8];
    const float* w1     = (const float*)d_in[9];
    const float* b1     = (const float*)d_in[10];
    const float* w2     = (const float*)d_in[11];
    const float* b2     = (const float*)d_in[12];
    float* out = (float*)d_out;

    cudaFuncSetAttribute(attn_kernel, cudaFuncAttributeMaxDynamicSharedMemorySize, ATT_SMEM_BYTES);
    cudaFuncSetAttribute(mlp_kernel,  cudaFuncAttributeMaxDynamicSharedMemorySize, MLP_SMEM_BYTES);

    attn_kernel<<<NBLKS, AT_THREADS, ATT_SMEM_BYTES>>>(x, qkv_w, qkv_b, proj_w, proj_b, g1, be1);
    mlp_kernel<<<(BATCH*NTOK)/TM, ML_THREADS, MLP_SMEM_BYTES>>>(g2, be2, w1, b1, w2, b2, out);
}

// round 5
// speedup vs baseline: 1.2447x; 1.0005x over previous
#include <cuda_runtime.h>
#include <math.h>
#include <mma.h>

using namespace nvcuda;

// ---------------- problem constants ----------------
#define DIMC   192
#define HW     56
#define WSZ    7
#define SHIFT  3
#define NHEADS 6
#define HD     32
#define HIDDEN 768
#define BATCH  32
#define NTOK   (HW*HW)          // 3136
#define NBLKS  (BATCH*64)       // 2048 windows
#define NTOKW  49

// ---------------- scratch ----------------
__device__ float g_xattn[(size_t)BATCH * NTOK * DIMC];

// ---------------- helpers ----------------
__device__ __forceinline__ float warp_sum(float v){
#pragma unroll
    for (int o = 16; o; o >>= 1) v += __shfl_xor_sync(0xffffffffu, v, o);
    return v;
}
__device__ __forceinline__ float warp_max(float v){
#pragma unroll
    for (int o = 16; o; o >>= 1) v = fmaxf(v, __shfl_xor_sync(0xffffffffu, v, o));
    return v;
}
__device__ __forceinline__ float gelu_exact(float x){
    return 0.5f * x * (1.0f + erff(x * 0.70710678118654752440f));
}

// ---------------- wmma tf32 helpers ----------------
typedef wmma::fragment<wmma::matrix_a, 16, 16, 8, wmma::precision::tf32, wmma::row_major> FragA;
typedef wmma::fragment<wmma::matrix_b, 16, 16, 8, wmma::precision::tf32, wmma::row_major> FragB;
typedef wmma::fragment<wmma::accumulator, 16, 16, 8, float> FragC;

__device__ __forceinline__ void load_a_tf32(FragA& f, const float* p, int ld){
    wmma::load_matrix_sync(f, p, ld);
#pragma unroll
    for (int i = 0; i < f.num_elements; i++) f.x[i] = wmma::__float_to_tf32(f.x[i]);
}
__device__ __forceinline__ void load_b_tf32(FragB& f, const float* p, int ld){
    wmma::load_matrix_sync(f, p, ld);
#pragma unroll
    for (int i = 0; i < f.num_elements; i++) f.x[i] = wmma::__float_to_tf32(f.x[i]);
}

// =====================================================================
// Kernel 1: shifted-window attention, one CTA per window. TF32 wmma for
// QKV + proj GEMMs; SIMT fp32 for S / softmax / PV.
// =====================================================================
#define AT_THREADS 384
#define SX  200     // s_x / s_o / output stride
#define QVS 40      // q/k/v stride
#define SBQ 104     // qkv B-stage stride
#define SBP 200     // proj B-stage stride
#define SST 56

// smem float offsets
#define OFF_X  0
#define OFF_O  (OFF_X + 64*SX)              // 12800
#define OFF_Q  (OFF_O + 64*SX)              // 25600
#define OFF_K  (OFF_Q + 64*QVS)             // 28160
#define OFF_V  (OFF_K + 64*QVS)             // 30720
#define OFF_S  (OFF_V + 64*QVS)             // 33280
#define OFF_B  (OFF_S + 64*SST)             // 36864
#define ATT_SMEM_FLOATS (OFF_B + 32*SBP)    // 43264
#define ATT_SMEM_BYTES  (ATT_SMEM_FLOATS*4) // 173056

__global__ __launch_bounds__(AT_THREADS)
void attn_kernel(const float* __restrict__ x,
                 const float* __restrict__ qkv_w, const float* __restrict__ qkv_b,
                 const float* __restrict__ proj_w, const float* __restrict__ proj_b,
                 const float* __restrict__ g1, const float* __restrict__ be1)
{
    extern __shared__ float sm[];
    float* s_x = sm + OFF_X;
    float* s_o = sm + OFF_O;
    float* s_q = sm + OFF_Q;
    float* s_k = sm + OFF_K;
    float* s_v = sm + OFF_V;
    float* s_S = sm + OFF_S;
    float* s_b = sm + OFF_B;

    const int t   = threadIdx.x;
    const int wid = t >> 5, lane = t & 31;
    const int blk = blockIdx.x;
    const int b   = blk >> 6;
    const int win = blk & 63;
    const int wr  = win >> 3, wc = win & 7;

    const float* xb = x + (size_t)b * NTOK * DIMC;

    // zero pad rows 49..63 of s_x and s_o
    for (int idx = t; idx < 15*SX; idx += AT_THREADS){
        s_x[49*SX + idx] = 0.f;
        s_o[49*SX + idx] = 0.f;
    }
    // gather with cyclic shift (roll -3,-3)
    for (int idx = t; idx < NTOKW*DIMC; idx += AT_THREADS){
        int row = idx / DIMC, c = idx - row*DIMC;
        int ti = row / WSZ, tj = row - ti*WSZ;
        int sr = wr*WSZ + ti + SHIFT; if (sr >= HW) sr -= HW;
        int sc = wc*WSZ + tj + SHIFT; if (sc >= HW) sc -= HW;
        s_x[row*SX + c] = xb[(sr*HW + sc)*DIMC + c];
    }
    __syncthreads();

    // LN1 in place (rows < 49)
    for (int r = wid; r < NTOKW; r += 12){
        float s = 0.f, s2 = 0.f;
#pragma unroll
        for (int c = lane; c < DIMC; c += 32){
            float v = s_x[r*SX + c]; s += v; s2 += v*v;
        }
        s = warp_sum(s); s2 = warp_sum(s2);
        float mu = s * (1.0f/DIMC);
        float rs = rsqrtf(s2*(1.0f/DIMC) - mu*mu + 1e-5f);
#pragma unroll
        for (int c = lane; c < DIMC; c += 32){
            float v = s_x[r*SX + c];
            s_x[r*SX + c] = (v - mu)*rs*g1[c] + be1[c];
        }
    }
    // (kc-loop top sync below orders LN before wmma reads)

    const int ti  = wid & 3;        // row tile 0..3
    const int pj  = wid >> 2;       // 0..2 : q / k / v group
    const int tj0 = 2*pj;

    for (int h = 0; h < NHEADS; h++){
        // ---- QKV slice [64,192] @ [192,96] ----
        FragC acc0, acc1;
        wmma::fill_fragment(acc0, 0.f);
        wmma::fill_fragment(acc1, 0.f);

        for (int kc = 0; kc < 6; kc++){
            __syncthreads();                 // s_b reuse + (first iter) LN order
            for (int idx = t; idx < 32*96; idx += AT_THREADS){
                int row = idx / 96, c = idx - row*96;
                int which = c >> 5, d = c & 31;
                s_b[row*SBQ + c] = qkv_w[(size_t)(kc*32 + row)*(3*DIMC) + which*DIMC + h*HD + d];
            }
            __syncthreads();
#pragma unroll
            for (int ks = 0; ks < 4; ks++){
                FragA fa; load_a_tf32(fa, s_x + ti*16*SX + kc*32 + ks*8, SX);
                FragB fb;
                load_b_tf32(fb, s_b + ks*8*SBQ + tj0*16, SBQ);
                wmma::mma_sync(acc0, fa, fb, acc0);
                load_b_tf32(fb, s_b + ks*8*SBQ + tj0*16 + 16, SBQ);
                wmma::mma_sync(acc1, fa, fb, acc1);
            }
        }
        {
            float* base = (pj == 0) ? s_q : (pj == 1) ? s_k : s_v;
            wmma::store_matrix_sync(base + ti*16*QVS + 0,  acc0, QVS, wmma::mem_row_major);
            wmma::store_matrix_sync(base + ti*16*QVS + 16, acc1, QVS, wmma::mem_row_major);
        }
        __syncthreads();

        // bias (general; zeros in this dataset)
        for (int idx = t; idx < NTOKW*96; idx += AT_THREADS){
            int row = idx / 96, c = idx - row*96;
            int which = c >> 5, d = c & 31;
            float* base = (which == 0) ? s_q : (which == 1) ? s_k : s_v;
            base[row*QVS + d] += qkv_b[which*DIMC + h*HD + d];
        }
        __syncthreads();

        // S = scale * q k^T  (SIMT)
        for (int idx = t; idx < NTOKW*NTOKW; idx += AT_THREADS){
            int i = idx / NTOKW, j = idx - i*NTOKW;
            const float* qi = s_q + i*QVS;
            const float* kj = s_k + j*QVS;
            float s = 0.f;
#pragma unroll
            for (int d2 = 0; d2 < HD; d2++) s += qi[d2]*kj[d2];
            s_S[i*SST + j] = s * 0.17677669529663688110f;
        }
        __syncthreads();

        // row softmax
        for (int r = wid; r < NTOKW; r += 12){
            float v0 = (lane      < NTOKW) ? s_S[r*SST + lane     ] : -1e30f;
            float v1 = (lane + 32 < NTOKW) ? s_S[r*SST + lane + 32] : -1e30f;
            float m  = warp_max(fmaxf(v0, v1));
            float e0 = (lane      < NTOKW) ? __expf(v0 - m) : 0.f;
            float e1 = (lane + 32 < NTOKW) ? __expf(v1 - m) : 0.f;
            float inv = 1.0f / warp_sum(e0 + e1);
            if (lane      < NTOKW) s_S[r*SST + lane     ] = e0 * inv;
            if (lane + 32 < NTOKW) s_S[r*SST + lane + 32] = e1 * inv;
        }
        __syncthreads();

        // O = P @ v -> cols [h*32, h*32+32) of s_o
        for (int idx = t; idx < NTOKW*HD; idx += AT_THREADS){
            int i = idx >> 5, d2 = idx & 31;
            const float* pi = s_S + i*SST;
            const float* vd = s_v + d2;
            float s = 0.f;
#pragma unroll
            for (int j = 0; j < NTOKW; j++) s += pi[j] * vd[j*QVS];
            s_o[i*SX + h*HD + d2] = s;
        }
        __syncthreads();
    }

    // ---- proj: [64,192] @ [192,192], wmma ----
    {
        const int c0 = wid >> 2;   // 0..2 ; warp's col tiles: c0, c0+3, c0+6, c0+9
        FragC pacc[4];
#pragma unroll
        for (int j = 0; j < 4; j++) wmma::fill_fragment(pacc[j], 0.f);

        for (int kc = 0; kc < 6; kc++){
            __syncthreads();
            for (int idx = t; idx < 32*DIMC; idx += AT_THREADS){
                int row = idx / DIMC, c = idx - row*DIMC;
                s_b[row*SBP + c] = proj_w[(size_t)(kc*32 + row)*DIMC + c];
            }
            __syncthreads();
#pragma unroll
            for (int ks = 0; ks < 4; ks++){
                FragA fa; load_a_tf32(fa, s_o + ti*16*SX + kc*32 + ks*8, SX);
#pragma unroll
                for (int j = 0; j < 4; j++){
                    FragB fb; load_b_tf32(fb, s_b + ks*8*SBP + (c0 + 3*j)*16, SBP);
                    wmma::mma_sync(pacc[j], fa, fb, pacc[j]);
                }
            }
        }
        __syncthreads();  // all mma readers of s_x long done; readers of s_o done
#pragma unroll
        for (int j = 0; j < 4; j++)
            wmma::store_matrix_sync(s_x + ti*16*SX + (c0 + 3*j)*16, pacc[j], SX, wmma::mem_row_major);
        __syncthreads();

        // scatter (roll +3,+3)
        float* ob = g_xattn + (size_t)b * NTOK * DIMC;
        for (int idx = t; idx < NTOKW*DIMC; idx += AT_THREADS){
            int row = idx / DIMC, c = idx - row*DIMC;
            int ti2 = row / WSZ, tj2 = row - ti2*WSZ;
            int sr = wr*WSZ + ti2 + SHIFT; if (sr >= HW) sr -= HW;
            int sc = wc*WSZ + tj2 + SHIFT; if (sc >= HW) sc -= HW;
            ob[(sr*HW + sc)*DIMC + c] = s_x[row*SX + c] + proj_b[c];
        }
    }
}

// =====================================================================
// Kernel 2: fused MLP (TF32 wmma). out = x + gelu(LN2(x)@w1+b1)@w2 + b2
// 64 tokens/CTA, hidden in 12 chunks of 64, hidden never hits HBM.
// =====================================================================
#define ML_THREADS 512
#define TM 64
#define TH 64
#define XNS 200
#define W1S 72
#define HS  72
#define W2S 200
#define MOFF_XN 0
#define MOFF_W1 (MOFF_XN + TM*XNS)          // 12800
#define MOFF_H  (MOFF_W1 + DIMC*W1S)        // 26624
#define MOFF_W2 (MOFF_H  + TM*HS)           // 31232
#define MLP_SMEM_FLOATS (MOFF_W2 + TH*W2S)  // 44032
#define MLP_SMEM_BYTES  (MLP_SMEM_FLOATS*4) // 176128

__global__ __launch_bounds__(ML_THREADS)
void mlp_kernel(const float* __restrict__ g2, const float* __restrict__ be2,
                const float* __restrict__ w1, const float* __restrict__ b1,
                const float* __restrict__ w2, const float* __restrict__ b2,
                float* __restrict__ out)
{
    extern __shared__ float sm[];
    float* s_xn = sm + MOFF_XN;   // [64][200]
    float* s_w1 = sm + MOFF_W1;   // [192][72] (64 cols used)
    float* s_h  = sm + MOFF_H;    // [64][72]
    float* s_w2 = sm + MOFF_W2;   // [64][200] (192 cols used)

    const int t = threadIdx.x;
    const int wid = t >> 5, lane = t & 31;
    const size_t tok0 = (size_t)blockIdx.x * TM;
    const float* xb = g_xattn + tok0 * DIMC;

    for (int idx = t; idx < TM*DIMC; idx += ML_THREADS){
        int r = idx / DIMC, c = idx - r*DIMC;
        s_xn[r*XNS + c] = xb[idx];
    }
    __syncthreads();

    // LN2 in place
    for (int r = wid; r < TM; r += 16){
        float s = 0.f, s2 = 0.f;
#pragma unroll
        for (int c = lane; c < DIMC; c += 32){
            float v = s_xn[r*XNS + c]; s += v; s2 += v*v;
        }
        s = warp_sum(s); s2 = warp_sum(s2);
        float mu = s * (1.0f/DIMC);
        float rs = rsqrtf(s2*(1.0f/DIMC) - mu*mu + 1e-5f);
#pragma unroll
        for (int c = lane; c < DIMC; c += 32){
            float v = s_xn[r*XNS + c];
            s_xn[r*XNS + c] = (v - mu)*rs*g2[c] + be2[c];
        }
    }

    // GEMM1 tiles: ti1 = wid>>2 (row), tj1 = wid&3 (col) over [4][4]
    // GEMM2 tiles: rw = wid&3 (row), cols cw, cw+4, cw+8 with cw = wid>>2
    const int ti1 = wid >> 2, tj1 = wid & 3;
    const int rw  = wid & 3,  cw  = wid >> 2;

    FragC acc2[3];
#pragma unroll
    for (int j = 0; j < 3; j++) wmma::fill_fragment(acc2[j], 0.f);

    for (int hc = 0; hc < 12; hc++){
        const int h0 = hc * TH;
        __syncthreads();   // protects s_w1/s_w2/s_h reuse; first iter orders LN

        for (int idx = t; idx < DIMC*TH; idx += ML_THREADS){
            int row = idx >> 6, c = idx & 63;
            s_w1[row*W1S + c] = w1[(size_t)row*HIDDEN + h0 + c];
        }
        for (int idx = t; idx < TH*DIMC; idx += ML_THREADS){
            int row = idx / DIMC, c = idx - row*DIMC;
            s_w2[row*W2S + c] = w2[(size_t)(h0 + row)*DIMC + c];
        }
        __syncthreads();

        // GEMM1: H[64,64] = Xn[64,192] @ W1c[192,64]
        FragC acc1;
        wmma::fill_fragment(acc1, 0.f);
#pragma unroll
        for (int ks = 0; ks < 24; ks++){
            FragA fa; load_a_tf32(fa, s_xn + ti1*16*XNS + ks*8, XNS);
            FragB fb; load_b_tf32(fb, s_w1 + ks*8*W1S + tj1*16, W1S);
            wmma::mma_sync(acc1, fa, fb, acc1);
        }
        wmma::store_matrix_sync(s_h + ti1*16*HS + tj1*16, acc1, HS, wmma::mem_row_major);
        __syncthreads();

        // bias + exact GELU
        for (int idx = t; idx < TM*TH; idx += ML_THREADS){
            int row = idx >> 6, c = idx & 63;
            float v = s_h[row*HS + c] + b1[h0 + c];
            s_h[row*HS + c] = gelu_exact(v);
        }
        __syncthreads();

        // GEMM2: acc2 += H[64,64] @ W2c[64,192]
#pragma unroll
        for (int ks = 0; ks < 8; ks++){
            FragA fa; load_a_tf32(fa, s_h + rw*16*HS + ks*8, HS);
#pragma unroll
            for (int j = 0; j < 3; j++){
                FragB fb; load_b_tf32(fb, s_w2 + ks*8*W2S + (cw + 4*j)*16, W2S);
                wmma::mma_sync(acc2[j], fa, fb, acc2[j]);
            }
        }
    }
    __syncthreads();  // all GEMM1 readers of s_xn done -> safe to overwrite
#pragma unroll
    for (int j = 0; j < 3; j++)
        wmma::store_matrix_sync(s_xn + rw*16*XNS + (cw + 4*j)*16, acc2[j], XNS, wmma::mem_row_major);
    __syncthreads();

    float* ob = out + tok0 * DIMC;
    for (int idx = t; idx < TM*DIMC; idx += ML_THREADS){
        int r = idx / DIMC, c = idx - r*DIMC;
        ob[idx] = s_xn[r*XNS + c] + b2[c] + xb[idx];   // +bias +residual
    }
}

// =====================================================================
// launch
// =====================================================================
extern "C" void kernel_launch(void* const* d_in, const int* in_sizes, int n_in,
                              void* d_out, int out_size)
{
    (void)in_sizes; (void)n_in; (void)out_size;
    const float* x      = (const float*)d_in[0];
    const float* qkv_w  = (const float*)d_in[1];
    const float* qkv_b  = (const float*)d_in[2];
    const float* proj_w = (const float*)d_in[3];
    const float* proj_b = (const float*)d_in[4];
    const float* g1     = (const float*)d_in[5];
    const float* be1    = (const float*)d_in[6];
    const float* g2     = (const float*)d_in[7];
    const float* be2    = (const float*)d_in[8];
    const float* w1     = (const float*)d_in[9];
    const float* b1     = (const float*)d_in[10];
    const float* w2     = (const float*)d_in[11];
    const float* b2     = (const float*)d_in[12];
    float* out = (float*)d_out;

    cudaFuncSetAttribute(attn_kernel, cudaFuncAttributeMaxDynamicSharedMemorySize, ATT_SMEM_BYTES);
    cudaFuncSetAttribute(mlp_kernel,  cudaFuncAttributeMaxDynamicSharedMemorySize, MLP_SMEM_BYTES);

    attn_kernel<<<NBLKS, AT_THREADS, ATT_SMEM_BYTES>>>(x, qkv_w, qkv_b, proj_w, proj_b, g1, be1);
    mlp_kernel<<<(BATCH*NTOK)/TM, ML_THREADS, MLP_SMEM_BYTES>>>(g2, be2, w1, b1, w2, b2, out);
}

// round 6
// speedup vs baseline: 1.4706x; 1.1815x over previous
#include <cuda_runtime.h>
#include <math.h>
#include <mma.h>

using namespace nvcuda;

// ---------------- problem constants ----------------
#define DIMC   192
#define HW     56
#define WSZ    7
#define SHIFT  3
#define NHEADS 6
#define HD     32
#define HIDDEN 768
#define BATCH  32
#define NTOK   (HW*HW)          // 3136
#define NBLKS  (BATCH*64)       // 2048 windows
#define NTOKW  49

// ---------------- scratch ----------------
__device__ float g_xattn[(size_t)BATCH * NTOK * DIMC];

// ---------------- helpers ----------------
__device__ __forceinline__ float warp_sum(float v){
#pragma unroll
    for (int o = 16; o; o >>= 1) v += __shfl_xor_sync(0xffffffffu, v, o);
    return v;
}
__device__ __forceinline__ float warp_max(float v){
#pragma unroll
    for (int o = 16; o; o >>= 1) v = fmaxf(v, __shfl_xor_sync(0xffffffffu, v, o));
    return v;
}
__device__ __forceinline__ float gelu_exact(float x){
    return 0.5f * x * (1.0f + erff(x * 0.70710678118654752440f));
}
__device__ __forceinline__ float4 cvt4(float4 v){
    v.x = wmma::__float_to_tf32(v.x); v.y = wmma::__float_to_tf32(v.y);
    v.z = wmma::__float_to_tf32(v.z); v.w = wmma::__float_to_tf32(v.w);
    return v;
}

typedef wmma::fragment<wmma::matrix_a, 16, 16, 8, wmma::precision::tf32, wmma::row_major> FragA;
typedef wmma::fragment<wmma::matrix_b, 16, 16, 8, wmma::precision::tf32, wmma::row_major> FragB;
typedef wmma::fragment<wmma::matrix_b, 16, 16, 8, wmma::precision::tf32, wmma::col_major> FragBt;
typedef wmma::fragment<wmma::accumulator, 16, 16, 8, float> FragC;

// =====================================================================
// Kernel 1: shifted-window attention, one CTA per window.
//  gather -> LN(tf32) -> QKV (3 wmma GEMMs, all heads) -> per-head:
//  S=QK^T (wmma, fp32 acc) -> softmax (fp32) -> PV (SIMT fp32, broadcast)
//  O overwrites Q smem -> proj (wmma) into K smem -> scatter.
// All tf32 conversions done once at smem-write time.
// =====================================================================
#define AT_THREADS 384
#define LD   200      // stride for s_x/s_q/s_k/s_v and staging
#define SLD  72       // stride for s_S

#define OFF_X  0
#define OFF_Q  (OFF_X + 64*LD)
#define OFF_K  (OFF_Q + 64*LD)
#define OFF_V  (OFF_K + 64*LD)
#define OFF_SB (OFF_V + 64*LD)                 // union: s_S (64*72) / s_b (32*200)
#define ATT_SMEM_FLOATS (OFF_SB + 32*LD)       // 57600 floats
#define ATT_SMEM_BYTES  (ATT_SMEM_FLOATS*4)    // 230400 B (< 227KB limit)

__global__ __launch_bounds__(AT_THREADS)
void attn_kernel(const float* __restrict__ x,
                 const float* __restrict__ qkv_w, const float* __restrict__ qkv_b,
                 const float* __restrict__ proj_w, const float* __restrict__ proj_b,
                 const float* __restrict__ g1, const float* __restrict__ be1)
{
    extern __shared__ float sm[];
    float* s_x = sm + OFF_X;
    float* s_q = sm + OFF_Q;     // Q -> later O (per head cols overwritten by PV)
    float* s_k = sm + OFF_K;     // K -> later proj output
    float* s_v = sm + OFF_V;
    float* s_S = sm + OFF_SB;    // scores (time-disjoint with s_b)
    float* s_b = sm + OFF_SB;    // weight staging

    const int t   = threadIdx.x;
    const int wid = t >> 5, lane = t & 31;
    const int blk = blockIdx.x;
    const int b   = blk >> 6;
    const int win = blk & 63;
    const int wr  = win >> 3, wc = win & 7;

    const float* xb = x + (size_t)b * NTOK * DIMC;

    // zero pad rows 49..63 of s_x (guarantees Q/K/V pad rows come out exactly 0)
    for (int idx = t; idx < 15*LD; idx += AT_THREADS) s_x[49*LD + idx] = 0.f;

    // gather with cyclic shift (roll -3,-3), float4
    for (int idx = t; idx < NTOKW*48; idx += AT_THREADS){
        int row = idx / 48, c4 = idx - row*48;
        int ti = row / WSZ, tj = row - ti*WSZ;
        int sr = wr*WSZ + ti + SHIFT; if (sr >= HW) sr -= HW;
        int sc = wc*WSZ + tj + SHIFT; if (sc >= HW) sc -= HW;
        *(float4*)(s_x + row*LD + c4*4) =
            *(const float4*)(xb + (size_t)(sr*HW + sc)*DIMC + c4*4);
    }
    __syncthreads();

    // LN1 in place (rows < 49), write tf32-rounded
    for (int r = wid; r < NTOKW; r += 12){
        float s = 0.f, s2 = 0.f;
#pragma unroll
        for (int c = lane; c < DIMC; c += 32){
            float v = s_x[r*LD + c]; s += v; s2 += v*v;
        }
        s = warp_sum(s); s2 = warp_sum(s2);
        float mu = s * (1.0f/DIMC);
        float rs = rsqrtf(s2*(1.0f/DIMC) - mu*mu + 1e-5f);
#pragma unroll
        for (int c = lane; c < DIMC; c += 32){
            float v = (s_x[r*LD + c] - mu)*rs*g1[c] + be1[c];
            s_x[r*LD + c] = wmma::__float_to_tf32(v);
        }
    }

    const int tr = wid & 3;        // row tile 0..3
    const int cg = wid >> 2;       // col group 0..2 -> cols cg, cg+3, cg+6, cg+9

    // ---- QKV: 3 GEMMs [64,192]@[192,192] (m = q/k/v) ----
    for (int m = 0; m < 3; m++){
        FragC acc[4];
#pragma unroll
        for (int j = 0; j < 4; j++) wmma::fill_fragment(acc[j], 0.f);

        for (int kc = 0; kc < 6; kc++){
            __syncthreads();   // s_b reuse (first iter also orders LN writes)
            for (int idx = t; idx < 32*48; idx += AT_THREADS){
                int row = idx / 48, c4 = idx - row*48;
                float4 v = *(const float4*)(qkv_w + (size_t)(kc*32 + row)*(3*DIMC)
                                            + m*DIMC + c4*4);
                *(float4*)(s_b + row*LD + c4*4) = cvt4(v);
            }
            __syncthreads();
#pragma unroll
            for (int ks = 0; ks < 4; ks++){
                FragA fa; wmma::load_matrix_sync(fa, s_x + tr*16*LD + kc*32 + ks*8, LD);
#pragma unroll
                for (int j = 0; j < 4; j++){
                    FragB fb; wmma::load_matrix_sync(fb, s_b + ks*8*LD + (cg + 3*j)*16, LD);
                    wmma::mma_sync(acc[j], fa, fb, acc[j]);
                }
            }
        }
        float* dst = (m == 0) ? s_q : (m == 1) ? s_k : s_v;
#pragma unroll
        for (int j = 0; j < 4; j++)
            wmma::store_matrix_sync(dst + tr*16*LD + (cg + 3*j)*16, acc[j], LD,
                                    wmma::mem_row_major);
    }
    __syncthreads();

    // bias; round q,k to tf32 (S gemm operands); v stays fp32 (PV is SIMT fp32)
    for (int idx = t; idx < NTOKW*DIMC; idx += AT_THREADS){
        int r = idx / DIMC, c = idx - r*DIMC;
        s_q[r*LD + c] = wmma::__float_to_tf32(s_q[r*LD + c] + qkv_b[c]);
        s_k[r*LD + c] = wmma::__float_to_tf32(s_k[r*LD + c] + qkv_b[DIMC + c]);
        s_v[r*LD + c] = s_v[r*LD + c] + qkv_b[2*DIMC + c];
    }
    __syncthreads();

    // ---- per-head attention ----
    for (int h = 0; h < NHEADS; h++){
        const float* qh = s_q + h*HD;
        const float* kh = s_k + h*HD;

        // S = scale * Q K^T  (wmma, fp32 accum). K pad rows are 0 -> S pad cols 0.
        for (int tile = wid; tile < 16; tile += 12){
            int ti2 = tile >> 2, tj2 = tile & 3;
            FragC sacc; wmma::fill_fragment(sacc, 0.f);
#pragma unroll
            for (int ks = 0; ks < 4; ks++){
                FragA fa;  wmma::load_matrix_sync(fa, qh + ti2*16*LD + ks*8, LD);
                FragBt fb; wmma::load_matrix_sync(fb, kh + tj2*16*LD + ks*8, LD);
                wmma::mma_sync(sacc, fa, fb, sacc);
            }
#pragma unroll
            for (int e = 0; e < sacc.num_elements; e++)
                sacc.x[e] *= 0.17677669529663688110f;
            wmma::store_matrix_sync(s_S + ti2*16*SLD + tj2*16, sacc, SLD,
                                    wmma::mem_row_major);
        }
        __syncthreads();

        // softmax (rows < 49, cols < 49), fp32
        for (int r = wid; r < NTOKW; r += 12){
            float v0 = (lane      < NTOKW) ? s_S[r*SLD + lane     ] : -1e30f;
            float v1 = (lane + 32 < NTOKW) ? s_S[r*SLD + lane + 32] : -1e30f;
            float m  = warp_max(fmaxf(v0, v1));
            float e0 = (lane      < NTOKW) ? __expf(v0 - m) : 0.f;
            float e1 = (lane + 32 < NTOKW) ? __expf(v1 - m) : 0.f;
            float inv = 1.0f / warp_sum(e0 + e1);
            if (lane      < NTOKW) s_S[r*SLD + lane     ] = e0 * inv;
            if (lane + 32 < NTOKW) s_S[r*SLD + lane + 32] = e1 * inv;
        }
        __syncthreads();

        // O_h = P @ V_h  (SIMT fp32: P broadcast across lanes, V coalesced).
        // Overwrites Q's head-h columns (Q_h no longer needed). Writes tf32
        // (rounded once here; proj consumes directly).
        {
            const float* vh = s_v + h*HD;
            float*       oh = s_q + h*HD;
            for (int i = wid; i < NTOKW; i += 12){
                const float* pr = s_S + i*SLD;
                float acc = 0.f;
#pragma unroll 7
                for (int j = 0; j < NTOKW; j++)
                    acc += pr[j] * vh[j*LD + lane];
                oh[i*LD + lane] = wmma::__float_to_tf32(acc);
            }
        }
        __syncthreads();
    }

    // ---- proj: [64,192]@[192,192] wmma; A = s_q (O, tf32; pad rows 0) ----
    {
        FragC acc[4];
#pragma unroll
        for (int j = 0; j < 4; j++) wmma::fill_fragment(acc[j], 0.f);

        for (int kc = 0; kc < 6; kc++){
            __syncthreads();   // also orders last PV reads of s_S before s_b overwrite
            for (int idx = t; idx < 32*48; idx += AT_THREADS){
                int row = idx / 48, c4 = idx - row*48;
                float4 v = *(const float4*)(proj_w + (size_t)(kc*32 + row)*DIMC + c4*4);
                *(float4*)(s_b + row*LD + c4*4) = cvt4(v);
            }
            __syncthreads();
#pragma unroll
            for (int ks = 0; ks < 4; ks++){
                FragA fa; wmma::load_matrix_sync(fa, s_q + tr*16*LD + kc*32 + ks*8, LD);
#pragma unroll
                for (int j = 0; j < 4; j++){
                    FragB fb; wmma::load_matrix_sync(fb, s_b + ks*8*LD + (cg + 3*j)*16, LD);
                    wmma::mma_sync(acc[j], fa, fb, acc[j]);
                }
            }
        }
#pragma unroll
        for (int j = 0; j < 4; j++)
            wmma::store_matrix_sync(s_k + tr*16*LD + (cg + 3*j)*16, acc[j], LD,
                                    wmma::mem_row_major);
        __syncthreads();

        // scatter (roll +3,+3) + proj bias, float4
        float* ob = g_xattn + (size_t)b * NTOK * DIMC;
        for (int idx = t; idx < NTOKW*48; idx += AT_THREADS){
            int row = idx / 48, c4 = idx - row*48;
            int ti2 = row / WSZ, tj2 = row - ti2*WSZ;
            int sr = wr*WSZ + ti2 + SHIFT; if (sr >= HW) sr -= HW;
            int sc = wc*WSZ + tj2 + SHIFT; if (sc >= HW) sc -= HW;
            float4 v  = *(float4*)(s_k + row*LD + c4*4);
            float4 pb = *(const float4*)(proj_b + c4*4);
            v.x += pb.x; v.y += pb.y; v.z += pb.z; v.w += pb.w;
            *(float4*)(ob + (size_t)(sr*HW + sc)*DIMC + c4*4) = v;
        }
    }
}

// =====================================================================
// Kernel 2: fused MLP.  out = x + gelu(LN2(x)@w1+b1)@w2 + b2
// 128 tokens/CTA (halves weight re-staging), hidden in 24 chunks of 32.
// =====================================================================
#define ML_THREADS 512
#define TM 128
#define TH 32
#define XLD 200
#define WLD 40
#define MO_XN 0
#define MO_W1 (MO_XN + TM*XLD)        // 25600
#define MO_H  (MO_W1 + DIMC*WLD)      // 33280
#define MO_W2 (MO_H  + TM*WLD)        // 38400
#define MLP_SMEM_FLOATS (MO_W2 + TH*XLD)   // 44800
#define MLP_SMEM_BYTES  (MLP_SMEM_FLOATS*4) // 179200

__global__ __launch_bounds__(ML_THREADS)
void mlp_kernel(const float* __restrict__ g2, const float* __restrict__ be2,
                const float* __restrict__ w1, const float* __restrict__ b1,
                const float* __restrict__ w2, const float* __restrict__ b2,
                float* __restrict__ out)
{
    extern __shared__ float sm[];
    float* s_xn = sm + MO_XN;   // [128][200]
    float* s_w1 = sm + MO_W1;   // [192][40] (32 cols used)
    float* s_h  = sm + MO_H;    // [128][40]
    float* s_w2 = sm + MO_W2;   // [32][200] (192 cols used)

    const int t = threadIdx.x;
    const int wid = t >> 5, lane = t & 31;
    const size_t tok0 = (size_t)blockIdx.x * TM;
    const float* xb = g_xattn + tok0 * DIMC;

    for (int idx = t; idx < TM*48; idx += ML_THREADS){
        int r = idx / 48, c4 = idx - r*48;
        *(float4*)(s_xn + r*XLD + c4*4) = *(const float4*)(xb + (size_t)r*DIMC + c4*4);
    }
    __syncthreads();

    // LN2, write tf32-rounded
    for (int r = wid; r < TM; r += 16){
        float s = 0.f, s2 = 0.f;
#pragma unroll
        for (int c = lane; c < DIMC; c += 32){
            float v = s_xn[r*XLD + c]; s += v; s2 += v*v;
        }
        s = warp_sum(s); s2 = warp_sum(s2);
        float mu = s * (1.0f/DIMC);
        float rs = rsqrtf(s2*(1.0f/DIMC) - mu*mu + 1e-5f);
#pragma unroll
        for (int c = lane; c < DIMC; c += 32){
            float v = (s_xn[r*XLD + c] - mu)*rs*g2[c] + be2[c];
            s_xn[r*XLD + c] = wmma::__float_to_tf32(v);
        }
    }

    const int r1  = wid & 7, c1  = wid >> 3;   // GEMM1: [8][2] tile grid
    const int rw  = wid & 7, cgg = wid >> 3;   // GEMM2: rows 8, cols cgg+2j

    FragC acc2[6];
#pragma unroll
    for (int j = 0; j < 6; j++) wmma::fill_fragment(acc2[j], 0.f);

    for (int hc = 0; hc < 24; hc++){
        const int h0 = hc * TH;
        __syncthreads();   // protect s_w1/s_w2/s_h; first iter orders LN

        // stage w1 chunk [192,32] (tf32)
        for (int idx = t; idx < 192*8; idx += ML_THREADS){
            int row = idx >> 3, c4 = idx & 7;
            float4 v = *(const float4*)(w1 + (size_t)row*HIDDEN + h0 + c4*4);
            *(float4*)(s_w1 + row*WLD + c4*4) = cvt4(v);
        }
        // stage w2 chunk [32,192] (tf32)
        for (int idx = t; idx < 32*48; idx += ML_THREADS){
            int row = idx / 48, c4 = idx - row*48;
            float4 v = *(const float4*)(w2 + (size_t)(h0 + row)*DIMC + c4*4);
            *(float4*)(s_w2 + row*XLD + c4*4) = cvt4(v);
        }
        __syncthreads();

        // GEMM1: H[128,32] = Xn[128,192] @ W1c
        FragC a1; wmma::fill_fragment(a1, 0.f);
#pragma unroll
        for (int ks = 0; ks < 24; ks++){
            FragA fa; wmma::load_matrix_sync(fa, s_xn + r1*16*XLD + ks*8, XLD);
            FragB fb; wmma::load_matrix_sync(fb, s_w1 + ks*8*WLD + c1*16, WLD);
            wmma::mma_sync(a1, fa, fb, a1);
        }
        wmma::store_matrix_sync(s_h + r1*16*WLD + c1*16, a1, WLD, wmma::mem_row_major);
        __syncwarp();
        // bias + exact GELU on this warp's own tile, write tf32
        {
            float* tb = s_h + r1*16*WLD + c1*16;
            const float* bp = b1 + h0 + c1*16;
#pragma unroll
            for (int e = lane; e < 256; e += 32){
                int rr = e >> 4, cc = e & 15;
                float v = tb[rr*WLD + cc] + bp[cc];
                tb[rr*WLD + cc] = wmma::__float_to_tf32(gelu_exact(v));
            }
        }
        __syncthreads();

        // GEMM2: acc2 += H[128,32] @ W2c[32,192]
#pragma unroll
        for (int ks = 0; ks < 4; ks++){
            FragA fa; wmma::load_matrix_sync(fa, s_h + rw*16*WLD + ks*8, WLD);
#pragma unroll
            for (int j = 0; j < 6; j++){
                FragB fb; wmma::load_matrix_sync(fb, s_w2 + ks*8*XLD + (cgg + 2*j)*16, XLD);
                wmma::mma_sync(acc2[j], fa, fb, acc2[j]);
            }
        }
    }
    __syncthreads();   // last GEMM1 readers of s_xn done
#pragma unroll
    for (int j = 0; j < 6; j++)
        wmma::store_matrix_sync(s_xn + rw*16*XLD + (cgg + 2*j)*16, acc2[j], XLD,
                                wmma::mem_row_major);
    __syncthreads();

    float* ob = out + tok0 * DIMC;
    for (int idx = t; idx < TM*48; idx += ML_THREADS){
        int r = idx / 48, c4 = idx - r*48;
        float4 a  = *(float4*)(s_xn + r*XLD + c4*4);
        float4 xr = *(const float4*)(xb + (size_t)r*DIMC + c4*4);
        float4 bb = *(const float4*)(b2 + c4*4);
        a.x += xr.x + bb.x; a.y += xr.y + bb.y;
        a.z += xr.z + bb.z; a.w += xr.w + bb.w;
        *(float4*)(ob + (size_t)r*DIMC + c4*4) = a;
    }
}

// =====================================================================
// launch
// =====================================================================
extern "C" void kernel_launch(void* const* d_in, const int* in_sizes, int n_in,
                              void* d_out, int out_size)
{
    (void)in_sizes; (void)n_in; (void)out_size;
    const float* x      = (const float*)d_in[0];
    const float* qkv_w  = (const float*)d_in[1];
    const float* qkv_b  = (const float*)d_in[2];
    const float* proj_w = (const float*)d_in[3];
    const float* proj_b = (const float*)d_in[4];
    const float* g1     = (const float*)d_in[5];
    const float* be1    = (const float*)d_in[6];
    const float* g2     = (const float*)d_in[7];
    const float* be2    = (const float*)d_in[8];
    const float* w1     = (const float*)d_in[9];
    const float* b1     = (const float*)d_in[10];
    const float* w2     = (const float*)d_in[11];
    const float* b2     = (const float*)d_in[12];
    float* out = (float*)d_out;

    cudaFuncSetAttribute(attn_kernel, cudaFuncAttributeMaxDynamicSharedMemorySize, ATT_SMEM_BYTES);
    cudaFuncSetAttribute(mlp_kernel,  cudaFuncAttributeMaxDynamicSharedMemorySize, MLP_SMEM_BYTES);

    attn_kernel<<<NBLKS, AT_THREADS, ATT_SMEM_BYTES>>>(x, qkv_w, qkv_b, proj_w, proj_b, g1, be1);
    mlp_kernel<<<(BATCH*NTOK)/TM, ML_THREADS, MLP_SMEM_BYTES>>>(g2, be2, w1, b1, w2, b2, out);
}

// round 8
// speedup vs baseline: 1.6638x; 1.1314x over previous
#include <cuda_runtime.h>
#include <cstdint>
#include <math.h>
#include <mma.h>

using namespace nvcuda;

// ---------------- problem constants ----------------
#define DIMC   192
#define HW     56
#define WSZ    7
#define SHIFT  3
#define NHEADS 6
#define HD     32
#define HIDDEN 768
#define BATCH  32
#define NTOK   (HW*HW)          // 3136
#define NBLKS  (BATCH*64)       // 2048 windows
#define NTOKW  49

// ---------------- scratch ----------------
__device__ float g_xattn[(size_t)BATCH * NTOK * DIMC];

// ---------------- helpers ----------------
__device__ __forceinline__ float warp_sum(float v){
#pragma unroll
    for (int o = 16; o; o >>= 1) v += __shfl_xor_sync(0xffffffffu, v, o);
    return v;
}
__device__ __forceinline__ float warp_max(float v){
#pragma unroll
    for (int o = 16; o; o >>= 1) v = fmaxf(v, __shfl_xor_sync(0xffffffffu, v, o));
    return v;
}
__device__ __forceinline__ float gelu_exact(float x){
    return 0.5f * x * (1.0f + erff(x * 0.70710678118654752440f));
}
__device__ __forceinline__ float4 cvt4(float4 v){
    v.x = wmma::__float_to_tf32(v.x); v.y = wmma::__float_to_tf32(v.y);
    v.z = wmma::__float_to_tf32(v.z); v.w = wmma::__float_to_tf32(v.w);
    return v;
}

// cp.async helpers
__device__ __forceinline__ void cp_async16(void* smem, const void* gmem){
    unsigned int s = (unsigned int)__cvta_generic_to_shared(smem);
    asm volatile("cp.async.cg.shared.global [%0], [%1], 16;\n" :: "r"(s), "l"(gmem));
}
__device__ __forceinline__ void cp_commit(){
    asm volatile("cp.async.commit_group;\n");
}
template<int N>
__device__ __forceinline__ void cp_wait(){
    asm volatile("cp.async.wait_group %0;\n" :: "n"(N));
}

typedef wmma::fragment<wmma::matrix_a, 16, 16, 8, wmma::precision::tf32, wmma::row_major> FragA;
typedef wmma::fragment<wmma::matrix_b, 16, 16, 8, wmma::precision::tf32, wmma::row_major> FragB;
typedef wmma::fragment<wmma::matrix_b, 16, 16, 8, wmma::precision::tf32, wmma::col_major> FragBt;
typedef wmma::fragment<wmma::accumulator, 16, 16, 8, float> FragC;

// =====================================================================
// Kernel 1: shifted-window attention, one CTA per window.
// gather -> LN(tf32) -> QKV (3 wmma GEMMs) -> head-groups of 3:
//   S (wmma) -> softmax (fp32, tf32 write) -> PV (wmma) into Q smem
// -> proj (wmma) into K smem -> scatter.
// =====================================================================
#define AT_THREADS 384
#define LD   200
#define SLD  72

#define OFF_Q  0
#define OFF_K  (64*LD)            // 12800
#define OFF_V  (128*LD)           // 25600
#define OFF_X  (192*LD)           // 38400  (gather/LN; later 3-head S buffer)
#define OFF_B  (256*LD)           // 51200  (32x200 weight staging)
#define ATT_SMEM_FLOATS (OFF_B + 32*LD)      // 57600
#define ATT_SMEM_BYTES  (ATT_SMEM_FLOATS*4)  // 230400

__global__ __launch_bounds__(AT_THREADS)
void attn_kernel(const float* __restrict__ x,
                 const float* __restrict__ qkv_w, const float* __restrict__ qkv_b,
                 const float* __restrict__ proj_w, const float* __restrict__ proj_b,
                 const float* __restrict__ g1, const float* __restrict__ be1)
{
    extern __shared__ float sm[];
    float* s_q = sm + OFF_Q;     // Q -> later O
    float* s_k = sm + OFF_K;     // K -> later proj output
    float* s_v = sm + OFF_V;
    float* s_x = sm + OFF_X;     // gather/LN input; dead after QKV
    float* s_S = sm + OFF_X;     // 3-head scores [3][64][72] (overlays s_x head)
    float* s_b = sm + OFF_B;     // weight staging [32][200]

    const int t   = threadIdx.x;
    const int wid = t >> 5, lane = t & 31;
    const int blk = blockIdx.x;
    const int b   = blk >> 6;
    const int win = blk & 63;
    const int wr  = win >> 3, wc = win & 7;

    const float* xb = x + (size_t)b * NTOK * DIMC;

    // zero pad rows 49..63 of s_x
    for (int idx = t; idx < 15*LD; idx += AT_THREADS) s_x[49*LD + idx] = 0.f;

    // gather with cyclic shift (roll -3,-3), float4
    for (int idx = t; idx < NTOKW*48; idx += AT_THREADS){
        int row = idx / 48, c4 = idx - row*48;
        int ti = row / WSZ, tj = row - ti*WSZ;
        int sr = wr*WSZ + ti + SHIFT; if (sr >= HW) sr -= HW;
        int sc = wc*WSZ + tj + SHIFT; if (sc >= HW) sc -= HW;
        *(float4*)(s_x + row*LD + c4*4) =
            *(const float4*)(xb + (size_t)(sr*HW + sc)*DIMC + c4*4);
    }
    __syncthreads();

    // LN1 in place (rows < 49), tf32 write
    for (int r = wid; r < NTOKW; r += 12){
        float s = 0.f, s2 = 0.f;
#pragma unroll
        for (int c = lane; c < DIMC; c += 32){
            float v = s_x[r*LD + c]; s += v; s2 += v*v;
        }
        s = warp_sum(s); s2 = warp_sum(s2);
        float mu = s * (1.0f/DIMC);
        float rs = rsqrtf(s2*(1.0f/DIMC) - mu*mu + 1e-5f);
#pragma unroll
        for (int c = lane; c < DIMC; c += 32){
            float v = (s_x[r*LD + c] - mu)*rs*g1[c] + be1[c];
            s_x[r*LD + c] = wmma::__float_to_tf32(v);
        }
    }

    // warp tiling for 64x192 GEMMs: 2 row-tiles x 2 col-tiles per warp
    const int rt0 = (wid / 6) * 2;   // row tiles rt0, rt0+1
    const int cgi = wid % 6;         // col tiles cgi, cgi+6

    // ---- QKV: 3 GEMMs [64,192]@[192,192] ----
    for (int m = 0; m < 3; m++){
        FragC acc[2][2];
#pragma unroll
        for (int i = 0; i < 2; i++)
#pragma unroll
            for (int j = 0; j < 2; j++) wmma::fill_fragment(acc[i][j], 0.f);

        for (int kc = 0; kc < 6; kc++){
            __syncthreads();   // s_b reuse; first iter orders LN
            for (int idx = t; idx < 32*48; idx += AT_THREADS){
                int row = idx / 48, c4 = idx - row*48;
                float4 v = *(const float4*)(qkv_w + (size_t)(kc*32 + row)*(3*DIMC)
                                            + m*DIMC + c4*4);
                *(float4*)(s_b + row*LD + c4*4) = cvt4(v);
            }
            __syncthreads();
#pragma unroll
            for (int ks = 0; ks < 4; ks++){
                FragA fa0, fa1;
                wmma::load_matrix_sync(fa0, s_x + (rt0  )*16*LD + kc*32 + ks*8, LD);
                wmma::load_matrix_sync(fa1, s_x + (rt0+1)*16*LD + kc*32 + ks*8, LD);
                FragB fb0, fb1;
                wmma::load_matrix_sync(fb0, s_b + ks*8*LD + cgi*16, LD);
                wmma::load_matrix_sync(fb1, s_b + ks*8*LD + (cgi+6)*16, LD);
                wmma::mma_sync(acc[0][0], fa0, fb0, acc[0][0]);
                wmma::mma_sync(acc[0][1], fa0, fb1, acc[0][1]);
                wmma::mma_sync(acc[1][0], fa1, fb0, acc[1][0]);
                wmma::mma_sync(acc[1][1], fa1, fb1, acc[1][1]);
            }
        }
        float* dst = (m == 0) ? s_q : (m == 1) ? s_k : s_v;
#pragma unroll
        for (int i = 0; i < 2; i++){
            wmma::store_matrix_sync(dst + (rt0+i)*16*LD + cgi*16,     acc[i][0], LD, wmma::mem_row_major);
            wmma::store_matrix_sync(dst + (rt0+i)*16*LD + (cgi+6)*16, acc[i][1], LD, wmma::mem_row_major);
        }
    }
    __syncthreads();

    // bias + tf32 round q,k,v (pad rows already exact 0)
    for (int idx = t; idx < NTOKW*DIMC; idx += AT_THREADS){
        int r = idx / DIMC, c = idx - r*DIMC;
        s_q[r*LD + c] = wmma::__float_to_tf32(s_q[r*LD + c] + qkv_b[c]);
        s_k[r*LD + c] = wmma::__float_to_tf32(s_k[r*LD + c] + qkv_b[DIMC + c]);
        s_v[r*LD + c] = wmma::__float_to_tf32(s_v[r*LD + c] + qkv_b[2*DIMC + c]);
    }
    __syncthreads();   // also: all QKV staging reads of s_x done -> s_S may overwrite

    // ---- head groups of 3 ----
    for (int g = 0; g < 2; g++){
        // S = scale * Q K^T for 3 heads: 48 tiles, 4 per warp
#pragma unroll
        for (int i = 0; i < 4; i++){
            int tt = wid + 12*i;
            int hh = tt >> 4, rem = tt & 15;
            int ti = rem >> 2, tj = rem & 3;
            int h = 3*g + hh;
            FragC sacc; wmma::fill_fragment(sacc, 0.f);
#pragma unroll
            for (int ks = 0; ks < 4; ks++){
                FragA fa;  wmma::load_matrix_sync(fa, s_q + h*HD + ti*16*LD + ks*8, LD);
                FragBt fb; wmma::load_matrix_sync(fb, s_k + h*HD + tj*16*LD + ks*8, LD);
                wmma::mma_sync(sacc, fa, fb, sacc);
            }
#pragma unroll
            for (int e = 0; e < sacc.num_elements; e++)
                sacc.x[e] *= 0.17677669529663688110f;
            wmma::store_matrix_sync(s_S + hh*64*SLD + ti*16*SLD + tj*16, sacc, SLD,
                                    wmma::mem_row_major);
        }
        __syncthreads();

        // softmax: 3*49 rows, fp32 math, tf32 write (cols>=49 stay exact 0)
        for (int rr = wid; rr < 3*NTOKW; rr += 12){
            int hh = rr / NTOKW, r = rr - hh*NTOKW;
            float* row = s_S + hh*64*SLD + r*SLD;
            float v0 = (lane      < NTOKW) ? row[lane     ] : -1e30f;
            float v1 = (lane + 32 < NTOKW) ? row[lane + 32] : -1e30f;
            float m  = warp_max(fmaxf(v0, v1));
            float e0 = (lane      < NTOKW) ? __expf(v0 - m) : 0.f;
            float e1 = (lane + 32 < NTOKW) ? __expf(v1 - m) : 0.f;
            float inv = 1.0f / warp_sum(e0 + e1);
            if (lane      < NTOKW) row[lane     ] = wmma::__float_to_tf32(e0 * inv);
            if (lane + 32 < NTOKW) row[lane + 32] = wmma::__float_to_tf32(e1 * inv);
        }
        __syncthreads();

        // PV: O_h[64,32] = P[64,64] @ V_h[64,32]; 24 tiles, 2 per warp.
        // Writes overwrite Q's head columns (tf32).
#pragma unroll
        for (int i = 0; i < 2; i++){
            int tt = wid + 12*i;
            int hh = tt >> 3, rem = tt & 7;
            int ti = rem >> 1, tj = rem & 1;
            int h = 3*g + hh;
            FragC oacc; wmma::fill_fragment(oacc, 0.f);
#pragma unroll
            for (int ks = 0; ks < 8; ks++){
                FragA fa; wmma::load_matrix_sync(fa, s_S + hh*64*SLD + ti*16*SLD + ks*8, SLD);
                FragB fb; wmma::load_matrix_sync(fb, s_v + h*HD + ks*8*LD + tj*16, LD);
                wmma::mma_sync(oacc, fa, fb, oacc);
            }
#pragma unroll
            for (int e = 0; e < oacc.num_elements; e++)
                oacc.x[e] = wmma::__float_to_tf32(oacc.x[e]);
            wmma::store_matrix_sync(s_q + h*HD + ti*16*LD + tj*16, oacc, LD,
                                    wmma::mem_row_major);
        }
        __syncthreads();
    }

    // ---- proj: [64,192]@[192,192]; A = s_q (O, tf32, pad rows 0) ----
    {
        FragC acc[2][2];
#pragma unroll
        for (int i = 0; i < 2; i++)
#pragma unroll
            for (int j = 0; j < 2; j++) wmma::fill_fragment(acc[i][j], 0.f);

        for (int kc = 0; kc < 6; kc++){
            __syncthreads();
            for (int idx = t; idx < 32*48; idx += AT_THREADS){
                int row = idx / 48, c4 = idx - row*48;
                float4 v = *(const float4*)(proj_w + (size_t)(kc*32 + row)*DIMC + c4*4);
                *(float4*)(s_b + row*LD + c4*4) = cvt4(v);
            }
            __syncthreads();
#pragma unroll
            for (int ks = 0; ks < 4; ks++){
                FragA fa0, fa1;
                wmma::load_matrix_sync(fa0, s_q + (rt0  )*16*LD + kc*32 + ks*8, LD);
                wmma::load_matrix_sync(fa1, s_q + (rt0+1)*16*LD + kc*32 + ks*8, LD);
                FragB fb0, fb1;
                wmma::load_matrix_sync(fb0, s_b + ks*8*LD + cgi*16, LD);
                wmma::load_matrix_sync(fb1, s_b + ks*8*LD + (cgi+6)*16, LD);
                wmma::mma_sync(acc[0][0], fa0, fb0, acc[0][0]);
                wmma::mma_sync(acc[0][1], fa0, fb1, acc[0][1]);
                wmma::mma_sync(acc[1][0], fa1, fb0, acc[1][0]);
                wmma::mma_sync(acc[1][1], fa1, fb1, acc[1][1]);
            }
        }
#pragma unroll
        for (int i = 0; i < 2; i++){
            wmma::store_matrix_sync(s_k + (rt0+i)*16*LD + cgi*16,     acc[i][0], LD, wmma::mem_row_major);
            wmma::store_matrix_sync(s_k + (rt0+i)*16*LD + (cgi+6)*16, acc[i][1], LD, wmma::mem_row_major);
        }
        __syncthreads();

        // scatter (roll +3,+3) + proj bias
        float* ob = g_xattn + (size_t)b * NTOK * DIMC;
        for (int idx = t; idx < NTOKW*48; idx += AT_THREADS){
            int row = idx / 48, c4 = idx - row*48;
            int ti2 = row / WSZ, tj2 = row - ti2*WSZ;
            int sr = wr*WSZ + ti2 + SHIFT; if (sr >= HW) sr -= HW;
            int sc = wc*WSZ + tj2 + SHIFT; if (sc >= HW) sc -= HW;
            float4 v  = *(float4*)(s_k + row*LD + c4*4);
            float4 pb = *(const float4*)(proj_b + c4*4);
            v.x += pb.x; v.y += pb.y; v.z += pb.z; v.w += pb.w;
            *(float4*)(ob + (size_t)(sr*HW + sc)*DIMC + c4*4) = v;
        }
    }
}

// =====================================================================
// Kernel 2: fused MLP with cp.async double-buffered weight staging.
// out = x + gelu(LN2(x)@w1+b1)@w2 + b2 ; 128 tokens/CTA, 24 chunks of 32.
// =====================================================================
#define ML_THREADS 512
#define TM 128
#define TH 32
#define XLD  196
#define W1LD 36
#define W2LD 196
#define W1BUF (192*W1LD)              // 6912 floats per buffer
#define W2BUF (32*W2LD)               // 6272
#define MO_XN 0
#define MO_W1 (MO_XN + TM*XLD)        // 25088
#define MO_H  (MO_W1 + 2*W1BUF)       // 38912
#define MO_W2 (MO_H  + TM*W1LD)       // 43520
#define MLP_SMEM_FLOATS (MO_W2 + 2*W2BUF)   // 56064
#define MLP_SMEM_BYTES  (MLP_SMEM_FLOATS*4) // 224256

__device__ __forceinline__ void mlp_stage(const float* __restrict__ w1,
                                          const float* __restrict__ w2,
                                          int h0, float* s_w1b, float* s_w2b, int t)
{
#pragma unroll
    for (int i = 0; i < 3; i++){       // w1 chunk [192][32]: 1536 float4
        int id = t + i*ML_THREADS;
        int row = id >> 3, c4 = id & 7;
        cp_async16(s_w1b + row*W1LD + c4*4, w1 + (size_t)row*HIDDEN + h0 + c4*4);
    }
#pragma unroll
    for (int i = 0; i < 3; i++){       // w2 chunk [32][192]: 1536 float4
        int id = t + i*ML_THREADS;
        int row = id / 48, c4 = id - row*48;
        cp_async16(s_w2b + row*W2LD + c4*4, w2 + (size_t)(h0 + row)*DIMC + c4*4);
    }
}
__device__ __forceinline__ void mlp_round(float* s_w1b, float* s_w2b, int t)
{
#pragma unroll
    for (int i = 0; i < 3; i++){
        int id = t + i*ML_THREADS;
        int row = id >> 3, c4 = id & 7;
        float4* p = (float4*)(s_w1b + row*W1LD + c4*4); *p = cvt4(*p);
    }
#pragma unroll
    for (int i = 0; i < 3; i++){
        int id = t + i*ML_THREADS;
        int row = id / 48, c4 = id - row*48;
        float4* p = (float4*)(s_w2b + row*W2LD + c4*4); *p = cvt4(*p);
    }
}

__global__ __launch_bounds__(ML_THREADS)
void mlp_kernel(const float* __restrict__ g2, const float* __restrict__ be2,
                const float* __restrict__ w1, const float* __restrict__ b1,
                const float* __restrict__ w2, const float* __restrict__ b2,
                float* __restrict__ out)
{
    extern __shared__ float sm[];
    float* s_xn = sm + MO_XN;   // [128][196]
    float* s_w1 = sm + MO_W1;   // 2 x [192][36]
    float* s_h  = sm + MO_H;    // [128][36]
    float* s_w2 = sm + MO_W2;   // 2 x [32][196]

    const int t = threadIdx.x;
    const int wid = t >> 5, lane = t & 31;
    const size_t tok0 = (size_t)blockIdx.x * TM;
    const float* xb = g_xattn + tok0 * DIMC;

    // kick off staging for chunks 0 and 1 (overlaps the x load + LN below)
    mlp_stage(w1, w2, 0,  s_w1,         s_w2,         t); cp_commit();
    mlp_stage(w1, w2, TH, s_w1 + W1BUF, s_w2 + W2BUF, t); cp_commit();

    for (int idx = t; idx < TM*48; idx += ML_THREADS){
        int r = idx / 48, c4 = idx - r*48;
        *(float4*)(s_xn + r*XLD + c4*4) = *(const float4*)(xb + (size_t)r*DIMC + c4*4);
    }
    __syncthreads();

    // LN2, tf32 write
    for (int r = wid; r < TM; r += 16){
        float s = 0.f, s2 = 0.f;
#pragma unroll
        for (int c = lane; c < DIMC; c += 32){
            float v = s_xn[r*XLD + c]; s += v; s2 += v*v;
        }
        s = warp_sum(s); s2 = warp_sum(s2);
        float mu = s * (1.0f/DIMC);
        float rs = rsqrtf(s2*(1.0f/DIMC) - mu*mu + 1e-5f);
#pragma unroll
        for (int c = lane; c < DIMC; c += 32){
            float v = (s_xn[r*XLD + c] - mu)*rs*g2[c] + be2[c];
            s_xn[r*XLD + c] = wmma::__float_to_tf32(v);
        }
    }

    const int r1 = wid & 7, c1 = wid >> 3;     // GEMM1: 8x2 tile grid, 1 tile/warp
    const int rw = wid & 7, cg2 = wid >> 3;    // GEMM2: rows 8; cols cg2+2j (6 tiles)

    FragC acc2[6];
#pragma unroll
    for (int j = 0; j < 6; j++) wmma::fill_fragment(acc2[j], 0.f);

    for (int hc = 0; hc < 24; hc++){
        const int cur = hc & 1;
        float* w1c = s_w1 + cur*W1BUF;
        float* w2c = s_w2 + cur*W2BUF;

        if (hc < 23) cp_wait<1>(); else cp_wait<0>();
        mlp_round(w1c, w2c, t);            // RN-round exactly what this thread copied
        __syncthreads();                   // staged+rounded data visible; (iter0: LN ordered)

        // GEMM1: H[128,32] = Xn[128,192] @ W1c[192,32]
        FragC a1; wmma::fill_fragment(a1, 0.f);
#pragma unroll
        for (int ks = 0; ks < 24; ks++){
            FragA fa; wmma::load_matrix_sync(fa, s_xn + r1*16*XLD + ks*8, XLD);
            FragB fb; wmma::load_matrix_sync(fb, w1c + ks*8*W1LD + c1*16, W1LD);
            wmma::mma_sync(a1, fa, fb, a1);
        }
        wmma::store_matrix_sync(s_h + r1*16*W1LD + c1*16, a1, W1LD, wmma::mem_row_major);
        __syncwarp();
        {   // bias + exact GELU on own tile, tf32 write
            float* tb = s_h + r1*16*W1LD + c1*16;
            const float* bp = b1 + hc*TH + c1*16;
#pragma unroll
            for (int e = lane; e < 256; e += 32){
                int rr2 = e >> 4, cc = e & 15;
                float v = tb[rr2*W1LD + cc] + bp[cc];
                tb[rr2*W1LD + cc] = wmma::__float_to_tf32(gelu_exact(v));
            }
        }
        __syncthreads();

        // GEMM2: acc2 += H[128,32] @ W2c[32,192]
#pragma unroll
        for (int ks = 0; ks < 4; ks++){
            FragA fa; wmma::load_matrix_sync(fa, s_h + rw*16*W1LD + ks*8, W1LD);
#pragma unroll
            for (int j = 0; j < 6; j++){
                FragB fb; wmma::load_matrix_sync(fb, w2c + ks*8*W2LD + (cg2 + 2*j)*16, W2LD);
                wmma::mma_sync(acc2[j], fa, fb, acc2[j]);
            }
        }
        __syncthreads();                   // all reads of cur buffers + s_h done

        if (hc + 2 < 24){                  // restage cur buffer for chunk hc+2
            mlp_stage(w1, w2, (hc+2)*TH, w1c, w2c, t);
            cp_commit();
        }
    }

    // epilogue: acc2 -> s_xn (overwrite), then residual + bias, coalesced out
#pragma unroll
    for (int j = 0; j < 6; j++)
        wmma::store_matrix_sync(s_xn + rw*16*XLD + (cg2 + 2*j)*16, acc2[j], XLD,
                                wmma::mem_row_major);
    __syncthreads();

    float* ob = out + tok0 * DIMC;
    for (int idx = t; idx < TM*48; idx += ML_THREADS){
        int r = idx / 48, c4 = idx - r*48;
        float4 a  = *(float4*)(s_xn + r*XLD + c4*4);
        float4 xr = *(const float4*)(xb + (size_t)r*DIMC + c4*4);
        float4 bb = *(const float4*)(b2 + c4*4);
        a.x += xr.x + bb.x; a.y += xr.y + bb.y;
        a.z += xr.z + bb.z; a.w += xr.w + bb.w;
        *(float4*)(ob + (size_t)r*DIMC + c4*4) = a;
    }
}

// =====================================================================
// launch
// =====================================================================
extern "C" void kernel_launch(void* const* d_in, const int* in_sizes, int n_in,
                              void* d_out, int out_size)
{
    (void)in_sizes; (void)n_in; (void)out_size;
    const float* x      = (const float*)d_in[0];
    const float* qkv_w  = (const float*)d_in[1];
    const float* qkv_b  = (const float*)d_in[2];
    const float* proj_w = (const float*)d_in[3];
    const float* proj_b = (const float*)d_in[4];
    const float* g1     = (const float*)d_in[5];
    const float* be1    = (const float*)d_in[6];
    const float* g2     = (const float*)d_in[7];
    const float* be2    = (const float*)d_in[8];
    const float* w1     = (const float*)d_in[9];
    const float* b1     = (const float*)d_in[10];
    const float* w2     = (const float*)d_in[11];
    const float* b2     = (const float*)d_in[12];
    float* out = (float*)d_out;

    cudaFuncSetAttribute(attn_kernel, cudaFuncAttributeMaxDynamicSharedMemorySize, ATT_SMEM_BYTES);
    cudaFuncSetAttribute(mlp_kernel,  cudaFuncAttributeMaxDynamicSharedMemorySize, MLP_SMEM_BYTES);

    attn_kernel<<<NBLKS, AT_THREADS, ATT_SMEM_BYTES>>>(x, qkv_w, qkv_b, proj_w, proj_b, g1, be1);
    mlp_kernel<<<(BATCH*NTOK)/TM, ML_THREADS, MLP_SMEM_BYTES>>>(g2, be2, w1, b1, w2, b2, out);
}

// round 10
// speedup vs baseline: 1.9885x; 1.1952x over previous
#include <cuda_runtime.h>
#include <cstdint>
#include <math.h>
#include <mma.h>

using namespace nvcuda;

// ---------------- problem constants ----------------
#define DIMC   192
#define HW     56
#define WSZ    7
#define SHIFT  3
#define NHEADS 6
#define HD     32
#define HIDDEN 768
#define BATCH  32
#define NTOK   (HW*HW)          // 3136
#define NBLKS  (BATCH*64)       // 2048 windows
#define NTOKW  49

// ---------------- scratch ----------------
__device__ float g_xattn[(size_t)BATCH * NTOK * DIMC];

// ---------------- helpers ----------------
__device__ __forceinline__ float warp_sum(float v){
#pragma unroll
    for (int o = 16; o; o >>= 1) v += __shfl_xor_sync(0xffffffffu, v, o);
    return v;
}
__device__ __forceinline__ float warp_max(float v){
#pragma unroll
    for (int o = 16; o; o >>= 1) v = fmaxf(v, __shfl_xor_sync(0xffffffffu, v, o));
    return v;
}
__device__ __forceinline__ float gelu_exact(float x){
    return 0.5f * x * (1.0f + erff(x * 0.70710678118654752440f));
}
__device__ __forceinline__ float4 cvt4(float4 v){
    v.x = wmma::__float_to_tf32(v.x); v.y = wmma::__float_to_tf32(v.y);
    v.z = wmma::__float_to_tf32(v.z); v.w = wmma::__float_to_tf32(v.w);
    return v;
}

// cp.async helpers
__device__ __forceinline__ void cp_async16(void* smem, const void* gmem){
    unsigned int s = (unsigned int)__cvta_generic_to_shared(smem);
    asm volatile("cp.async.cg.shared.global [%0], [%1], 16;\n" :: "r"(s), "l"(gmem));
}
__device__ __forceinline__ void cp_commit(){
    asm volatile("cp.async.commit_group;\n");
}
template<int N>
__device__ __forceinline__ void cp_wait(){
    asm volatile("cp.async.wait_group %0;\n" :: "n"(N));
}

typedef wmma::fragment<wmma::matrix_a, 16, 16, 8, wmma::precision::tf32, wmma::row_major> FragA;
typedef wmma::fragment<wmma::matrix_b, 16, 16, 8, wmma::precision::tf32, wmma::row_major> FragB;
typedef wmma::fragment<wmma::matrix_b, 16, 16, 8, wmma::precision::tf32, wmma::col_major> FragBt;
typedef wmma::fragment<wmma::accumulator, 16, 16, 8, float> FragC;

// =====================================================================
// Kernel 1: shifted-window attention, one CTA per window.
// Conflict-free strides: A-operands stride%32==4 (196/68), B-operands
// stride%32==8 (200). Weight staging via register prefetch (unified
// 24-chunk stream: 18 QKV + 6 proj).
// =====================================================================
#define AT_THREADS 384
#define LD   196      // s_x / s_q / s_k (A-operand friendly: 196%32==4)
#define VLD  200      // s_v (B-operand friendly: 200%32==8)
#define SLD  68       // scores (A-operand friendly: 68%32==4)
#define BLD  200      // weight staging (B-operand friendly)

#define OFF_Q  0
#define OFF_K  (64*LD)                 // 12544
#define OFF_V  (128*LD)                // 25088
#define OFF_X  (OFF_V + 64*VLD)        // 37888 (gather/LN; later S buffer)
#define OFF_B  (OFF_X + 64*LD)         // 50432 (32x200 staging)
#define ATT_SMEM_FLOATS (OFF_B + 32*BLD)     // 56832
#define ATT_SMEM_BYTES  (ATT_SMEM_FLOATS*4)  // 227328  (fits 227KB opt-in)
// s_S = sm + OFF_X needs 3*64*68 = 13056 <= 64*LD + 32*BLD = 18944 (both dead then)

__global__ __launch_bounds__(AT_THREADS)
void attn_kernel(const float* __restrict__ x,
                 const float* __restrict__ qkv_w, const float* __restrict__ qkv_b,
                 const float* __restrict__ proj_w, const float* __restrict__ proj_b,
                 const float* __restrict__ g1, const float* __restrict__ be1)
{
    extern __shared__ float sm[];
    float* s_q = sm + OFF_Q;     // Q -> later O
    float* s_k = sm + OFF_K;     // K -> later proj output
    float* s_v = sm + OFF_V;
    float* s_x = sm + OFF_X;     // gather/LN input; dead after QKV
    float* s_S = sm + OFF_X;     // 3-head scores [3][64][68]
    float* s_b = sm + OFF_B;     // weight staging [32][200]

    const int t   = threadIdx.x;
    const int wid = t >> 5, lane = t & 31;
    const int blk = blockIdx.x;
    const int b   = blk >> 6;
    const int win = blk & 63;
    const int wr  = win >> 3, wc = win & 7;

    const float* xb = x + (size_t)b * NTOK * DIMC;

    // per-thread staging coords: 1536 float4 per chunk / 384 threads = 4 each
    int prow[4], pc4[4];
#pragma unroll
    for (int i = 0; i < 4; i++){
        int idx = t + i*AT_THREADS;
        prow[i] = idx / 48; pc4[i] = idx - prow[i]*48;
    }
    float4 pf[4];

    // prefetch chunk 0 (m=0, kc=0 of qkv)
#pragma unroll
    for (int i = 0; i < 4; i++)
        pf[i] = *(const float4*)(qkv_w + (size_t)prow[i]*(3*DIMC) + pc4[i]*4);

    // zero pad rows 49..63 of s_x
    for (int idx = t; idx < 15*LD; idx += AT_THREADS) s_x[49*LD + idx] = 0.f;

    // gather with cyclic shift (roll -3,-3), float4
    for (int idx = t; idx < NTOKW*48; idx += AT_THREADS){
        int row = idx / 48, c4 = idx - row*48;
        int ti = row / WSZ, tj = row - ti*WSZ;
        int sr = wr*WSZ + ti + SHIFT; if (sr >= HW) sr -= HW;
        int sc = wc*WSZ + tj + SHIFT; if (sc >= HW) sc -= HW;
        *(float4*)(s_x + row*LD + c4*4) =
            *(const float4*)(xb + (size_t)(sr*HW + sc)*DIMC + c4*4);
    }
    __syncthreads();

    // LN1 in place (rows < 49), tf32 write
    for (int r = wid; r < NTOKW; r += 12){
        float s = 0.f, s2 = 0.f;
#pragma unroll
        for (int c = lane; c < DIMC; c += 32){
            float v = s_x[r*LD + c]; s += v; s2 += v*v;
        }
        s = warp_sum(s); s2 = warp_sum(s2);
        float mu = s * (1.0f/DIMC);
        float rs = rsqrtf(s2*(1.0f/DIMC) - mu*mu + 1e-5f);
#pragma unroll
        for (int c = lane; c < DIMC; c += 32){
            float v = (s_x[r*LD + c] - mu)*rs*g1[c] + be1[c];
            s_x[r*LD + c] = wmma::__float_to_tf32(v);
        }
    }

    // warp tiling for 64x192 GEMMs: 2 row-tiles x 2 col-tiles per warp
    const int rt0 = (wid / 6) * 2;   // row tiles rt0, rt0+1
    const int cgi = wid % 6;         // col tiles cgi, cgi+6

    int ci = 0;   // chunk stream position (0..23)

    // ---- QKV: 3 GEMMs [64,192]@[192,192] ----
    for (int m = 0; m < 3; m++){
        FragC acc[2][2];
#pragma unroll
        for (int i = 0; i < 2; i++)
#pragma unroll
            for (int j = 0; j < 2; j++) wmma::fill_fragment(acc[i][j], 0.f);

        for (int kc = 0; kc < 6; kc++){
            __syncthreads();   // previous chunk's mma readers of s_b done
#pragma unroll
            for (int i = 0; i < 4; i++)
                *(float4*)(s_b + prow[i]*BLD + pc4[i]*4) = cvt4(pf[i]);
            ci++;
            if (ci < 18){           // next qkv chunk
                int m2 = ci / 6, kc2 = ci - m2*6;
                const float* base = qkv_w + (size_t)(kc2*32)*(3*DIMC) + m2*DIMC;
#pragma unroll
                for (int i = 0; i < 4; i++)
                    pf[i] = *(const float4*)(base + (size_t)prow[i]*(3*DIMC) + pc4[i]*4);
            } else if (ci < 24){    // proj chunk
                int kc2 = ci - 18;
                const float* base = proj_w + (size_t)(kc2*32)*DIMC;
#pragma unroll
                for (int i = 0; i < 4; i++)
                    pf[i] = *(const float4*)(base + (size_t)prow[i]*DIMC + pc4[i]*4);
            }
            __syncthreads();
#pragma unroll
            for (int ks = 0; ks < 4; ks++){
                FragA fa0, fa1;
                wmma::load_matrix_sync(fa0, s_x + (rt0  )*16*LD + kc*32 + ks*8, LD);
                wmma::load_matrix_sync(fa1, s_x + (rt0+1)*16*LD + kc*32 + ks*8, LD);
                FragB fb0, fb1;
                wmma::load_matrix_sync(fb0, s_b + ks*8*BLD + cgi*16, BLD);
                wmma::load_matrix_sync(fb1, s_b + ks*8*BLD + (cgi+6)*16, BLD);
                wmma::mma_sync(acc[0][0], fa0, fb0, acc[0][0]);
                wmma::mma_sync(acc[0][1], fa0, fb1, acc[0][1]);
                wmma::mma_sync(acc[1][0], fa1, fb0, acc[1][0]);
                wmma::mma_sync(acc[1][1], fa1, fb1, acc[1][1]);
            }
        }
        float* dst = (m == 0) ? s_q : (m == 1) ? s_k : s_v;
        const int dstld = (m == 2) ? VLD : LD;
#pragma unroll
        for (int i = 0; i < 2; i++){
            wmma::store_matrix_sync(dst + (rt0+i)*16*dstld + cgi*16,     acc[i][0], dstld, wmma::mem_row_major);
            wmma::store_matrix_sync(dst + (rt0+i)*16*dstld + (cgi+6)*16, acc[i][1], dstld, wmma::mem_row_major);
        }
    }
    __syncthreads();

    // bias + tf32 round q,k,v (pad rows already exact 0)
    for (int idx = t; idx < NTOKW*DIMC; idx += AT_THREADS){
        int r = idx / DIMC, c = idx - r*DIMC;
        s_q[r*LD  + c] = wmma::__float_to_tf32(s_q[r*LD  + c] + qkv_b[c]);
        s_k[r*LD  + c] = wmma::__float_to_tf32(s_k[r*LD  + c] + qkv_b[DIMC + c]);
        s_v[r*VLD + c] = wmma::__float_to_tf32(s_v[r*VLD + c] + qkv_b[2*DIMC + c]);
    }
    __syncthreads();   // also: QKV phase reads of s_x done -> s_S may overwrite

    // ---- head groups of 3 ----
    for (int g = 0; g < 2; g++){
        // S = scale * Q K^T for 3 heads: 48 tiles, 4 per warp
#pragma unroll
        for (int i = 0; i < 4; i++){
            int tt = wid + 12*i;
            int hh = tt >> 4, rem = tt & 15;
            int ti = rem >> 2, tj = rem & 3;
            int h = 3*g + hh;
            FragC sacc; wmma::fill_fragment(sacc, 0.f);
#pragma unroll
            for (int ks = 0; ks < 4; ks++){
                FragA fa;  wmma::load_matrix_sync(fa, s_q + h*HD + ti*16*LD + ks*8, LD);
                FragBt fb; wmma::load_matrix_sync(fb, s_k + h*HD + tj*16*LD + ks*8, LD);
                wmma::mma_sync(sacc, fa, fb, sacc);
            }
#pragma unroll
            for (int e = 0; e < sacc.num_elements; e++)
                sacc.x[e] *= 0.17677669529663688110f;
            wmma::store_matrix_sync(s_S + hh*64*SLD + ti*16*SLD + tj*16, sacc, SLD,
                                    wmma::mem_row_major);
        }
        __syncthreads();

        // softmax: 3*49 rows, fp32 math, tf32 write (cols>=49 stay exact 0)
        for (int rr = wid; rr < 3*NTOKW; rr += 12){
            int hh = rr / NTOKW, r = rr - hh*NTOKW;
            float* row = s_S + hh*64*SLD + r*SLD;
            float v0 = (lane      < NTOKW) ? row[lane     ] : -1e30f;
            float v1 = (lane + 32 < NTOKW) ? row[lane + 32] : -1e30f;
            float m  = warp_max(fmaxf(v0, v1));
            float e0 = (lane      < NTOKW) ? __expf(v0 - m) : 0.f;
            float e1 = (lane + 32 < NTOKW) ? __expf(v1 - m) : 0.f;
            float inv = 1.0f / warp_sum(e0 + e1);
            if (lane      < NTOKW) row[lane     ] = wmma::__float_to_tf32(e0 * inv);
            if (lane + 32 < NTOKW) row[lane + 32] = wmma::__float_to_tf32(e1 * inv);
        }
        __syncthreads();

        // PV: O_h[64,32] = P[64,64] @ V_h[64,32]; 24 tiles, 2 per warp.
#pragma unroll
        for (int i = 0; i < 2; i++){
            int tt = wid + 12*i;
            int hh = tt >> 3, rem = tt & 7;
            int ti = rem >> 1, tj = rem & 1;
            int h = 3*g + hh;
            FragC oacc; wmma::fill_fragment(oacc, 0.f);
#pragma unroll
            for (int ks = 0; ks < 8; ks++){
                FragA fa; wmma::load_matrix_sync(fa, s_S + hh*64*SLD + ti*16*SLD + ks*8, SLD);
                FragB fb; wmma::load_matrix_sync(fb, s_v + h*HD + ks*8*VLD + tj*16, VLD);
                wmma::mma_sync(oacc, fa, fb, oacc);
            }
#pragma unroll
            for (int e = 0; e < oacc.num_elements; e++)
                oacc.x[e] = wmma::__float_to_tf32(oacc.x[e]);
            wmma::store_matrix_sync(s_q + h*HD + ti*16*LD + tj*16, oacc, LD,
                                    wmma::mem_row_major);
        }
        __syncthreads();
    }

    // ---- proj: [64,192]@[192,192]; A = s_q (O, tf32, pad rows 0) ----
    {
        FragC acc[2][2];
#pragma unroll
        for (int i = 0; i < 2; i++)
#pragma unroll
            for (int j = 0; j < 2; j++) wmma::fill_fragment(acc[i][j], 0.f);

        for (int kc = 0; kc < 6; kc++){
            __syncthreads();   // PV reads of s_S (overlaps s_b) / prev mma done
#pragma unroll
            for (int i = 0; i < 4; i++)
                *(float4*)(s_b + prow[i]*BLD + pc4[i]*4) = cvt4(pf[i]);
            ci++;
            if (ci < 24){
                int kc2 = ci - 18;
                const float* base = proj_w + (size_t)(kc2*32)*DIMC;
#pragma unroll
                for (int i = 0; i < 4; i++)
                    pf[i] = *(const float4*)(base + (size_t)prow[i]*DIMC + pc4[i]*4);
            }
            __syncthreads();
#pragma unroll
            for (int ks = 0; ks < 4; ks++){
                FragA fa0, fa1;
                wmma::load_matrix_sync(fa0, s_q + (rt0  )*16*LD + kc*32 + ks*8, LD);
                wmma::load_matrix_sync(fa1, s_q + (rt0+1)*16*LD + kc*32 + ks*8, LD);
                FragB fb0, fb1;
                wmma::load_matrix_sync(fb0, s_b + ks*8*BLD + cgi*16, BLD);
                wmma::load_matrix_sync(fb1, s_b + ks*8*BLD + (cgi+6)*16, BLD);
                wmma::mma_sync(acc[0][0], fa0, fb0, acc[0][0]);
                wmma::mma_sync(acc[0][1], fa0, fb1, acc[0][1]);
                wmma::mma_sync(acc[1][0], fa1, fb0, acc[1][0]);
                wmma::mma_sync(acc[1][1], fa1, fb1, acc[1][1]);
            }
        }
#pragma unroll
        for (int i = 0; i < 2; i++){
            wmma::store_matrix_sync(s_k + (rt0+i)*16*LD + cgi*16,     acc[i][0], LD, wmma::mem_row_major);
            wmma::store_matrix_sync(s_k + (rt0+i)*16*LD + (cgi+6)*16, acc[i][1], LD, wmma::mem_row_major);
        }
        __syncthreads();

        // scatter (roll +3,+3) + proj bias
        float* ob = g_xattn + (size_t)b * NTOK * DIMC;
        for (int idx = t; idx < NTOKW*48; idx += AT_THREADS){
            int row = idx / 48, c4 = idx - row*48;
            int ti2 = row / WSZ, tj2 = row - ti2*WSZ;
            int sr = wr*WSZ + ti2 + SHIFT; if (sr >= HW) sr -= HW;
            int sc = wc*WSZ + tj2 + SHIFT; if (sc >= HW) sc -= HW;
            float4 v  = *(float4*)(s_k + row*LD + c4*4);
            float4 pb = *(const float4*)(proj_b + c4*4);
            v.x += pb.x; v.y += pb.y; v.z += pb.z; v.w += pb.w;
            *(float4*)(ob + (size_t)(sr*HW + sc)*DIMC + c4*4) = v;
        }
    }
}

// =====================================================================
// Kernel 2: fused MLP with cp.async double-buffered weights.
// Conflict-free strides: A stride%32==4 (196/36), B stride%32==8 (40/200).
// GEMM1: 2 independent k-chains; GEMM2: 2x3 warp tile for B reuse.
// =====================================================================
#define ML_THREADS 512
#define TM 128
#define TH 32
#define XLD  196
#define W1LD 40
#define HLD  36
#define W2LD 200
#define W1BUF (192*W1LD)              // 7680 floats per buffer
#define W2BUF (32*W2LD)               // 6400
#define MO_XN 0
#define MO_W1 (MO_XN + TM*XLD)        // 25088
#define MO_H  (MO_W1 + 2*W1BUF)       // 40448
#define MO_W2 (MO_H  + TM*HLD)        // 45056
#define MLP_SMEM_FLOATS (MO_W2 + 2*W2BUF)   // 57856
#define MLP_SMEM_BYTES  (MLP_SMEM_FLOATS*4) // 231424 (fits 227KB opt-in)

__device__ __forceinline__ void mlp_stage(const float* __restrict__ w1,
                                          const float* __restrict__ w2,
                                          int h0, float* s_w1b, float* s_w2b, int t)
{
#pragma unroll
    for (int i = 0; i < 3; i++){       // w1 chunk [192][32]: 1536 float4
        int id = t + i*ML_THREADS;
        int row = id >> 3, c4 = id & 7;
        cp_async16(s_w1b + row*W1LD + c4*4, w1 + (size_t)row*HIDDEN + h0 + c4*4);
    }
#pragma unroll
    for (int i = 0; i < 3; i++){       // w2 chunk [32][192]: 1536 float4
        int id = t + i*ML_THREADS;
        int row = id / 48, c4 = id - row*48;
        cp_async16(s_w2b + row*W2LD + c4*4, w2 + (size_t)(h0 + row)*DIMC + c4*4);
    }
}
__device__ __forceinline__ void mlp_round(float* s_w1b, float* s_w2b, int t)
{
#pragma unroll
    for (int i = 0; i < 3; i++){
        int id = t + i*ML_THREADS;
        int row = id >> 3, c4 = id & 7;
        float4* p = (float4*)(s_w1b + row*W1LD + c4*4); *p = cvt4(*p);
    }
#pragma unroll
    for (int i = 0; i < 3; i++){
        int id = t + i*ML_THREADS;
        int row = id / 48, c4 = id - row*48;
        float4* p = (float4*)(s_w2b + row*W2LD + c4*4); *p = cvt4(*p);
    }
}

__global__ __launch_bounds__(ML_THREADS)
void mlp_kernel(const float* __restrict__ g2, const float* __restrict__ be2,
                const float* __restrict__ w1, const float* __restrict__ b1,
                const float* __restrict__ w2, const float* __restrict__ b2,
                float* __restrict__ out)
{
    extern __shared__ float sm[];
    float* s_xn = sm + MO_XN;   // [128][196]
    float* s_w1 = sm + MO_W1;   // 2 x [192][40]
    float* s_h  = sm + MO_H;    // [128][36]
    float* s_w2 = sm + MO_W2;   // 2 x [32][200]

    const int t = threadIdx.x;
    const int wid = t >> 5, lane = t & 31;
    const size_t tok0 = (size_t)blockIdx.x * TM;
    const float* xb = g_xattn + tok0 * DIMC;

    // kick off staging for chunks 0 and 1 (overlaps x load + LN)
    mlp_stage(w1, w2, 0,  s_w1,         s_w2,         t); cp_commit();
    mlp_stage(w1, w2, TH, s_w1 + W1BUF, s_w2 + W2BUF, t); cp_commit();

    for (int idx = t; idx < TM*48; idx += ML_THREADS){
        int r = idx / 48, c4 = idx - r*48;
        *(float4*)(s_xn + r*XLD + c4*4) = *(const float4*)(xb + (size_t)r*DIMC + c4*4);
    }
    __syncthreads();

    // LN2, tf32 write
    for (int r = wid; r < TM; r += 16){
        float s = 0.f, s2 = 0.f;
#pragma unroll
        for (int c = lane; c < DIMC; c += 32){
            float v = s_xn[r*XLD + c]; s += v; s2 += v*v;
        }
        s = warp_sum(s); s2 = warp_sum(s2);
        float mu = s * (1.0f/DIMC);
        float rs = rsqrtf(s2*(1.0f/DIMC) - mu*mu + 1e-5f);
#pragma unroll
        for (int c = lane; c < DIMC; c += 32){
            float v = (s_xn[r*XLD + c] - mu)*rs*g2[c] + be2[c];
            s_xn[r*XLD + c] = wmma::__float_to_tf32(v);
        }
    }

    const int r1 = wid & 7, c1 = wid >> 3;     // GEMM1: 8x2 grid, 1 tile/warp
    const int rp = wid & 3, cp = wid >> 2;     // GEMM2: 2x3 tiles/warp (4x4 warp grid)

    FragC acc2[2][3];
#pragma unroll
    for (int i = 0; i < 2; i++)
#pragma unroll
        for (int j = 0; j < 3; j++) wmma::fill_fragment(acc2[i][j], 0.f);

    for (int hc = 0; hc < 24; hc++){
        const int cur = hc & 1;
        float* w1c = s_w1 + cur*W1BUF;
        float* w2c = s_w2 + cur*W2BUF;

        if (hc < 23) cp_wait<1>(); else cp_wait<0>();
        mlp_round(w1c, w2c, t);            // thread rounds exactly what it copied
        __syncthreads();

        // GEMM1: H[128,32] = Xn[128,192] @ W1c[192,32]; 2 independent chains
        FragC a1e, a1o;
        wmma::fill_fragment(a1e, 0.f);
        wmma::fill_fragment(a1o, 0.f);
#pragma unroll
        for (int ks = 0; ks < 12; ks++){
            FragA fae, fao; FragB fbe, fbo;
            wmma::load_matrix_sync(fae, s_xn + r1*16*XLD + (2*ks  )*8, XLD);
            wmma::load_matrix_sync(fbe, w1c + (2*ks  )*8*W1LD + c1*16, W1LD);
            wmma::load_matrix_sync(fao, s_xn + r1*16*XLD + (2*ks+1)*8, XLD);
            wmma::load_matrix_sync(fbo, w1c + (2*ks+1)*8*W1LD + c1*16, W1LD);
            wmma::mma_sync(a1e, fae, fbe, a1e);
            wmma::mma_sync(a1o, fao, fbo, a1o);
        }
#pragma unroll
        for (int e = 0; e < a1e.num_elements; e++) a1e.x[e] += a1o.x[e];
        wmma::store_matrix_sync(s_h + r1*16*HLD + c1*16, a1e, HLD, wmma::mem_row_major);
        __syncwarp();
        {   // bias + exact GELU on own tile, tf32 write
            float* tb = s_h + r1*16*HLD + c1*16;
            const float* bp = b1 + hc*TH + c1*16;
#pragma unroll
            for (int e = lane; e < 256; e += 32){
                int rr2 = e >> 4, cc = e & 15;
                float v = tb[rr2*HLD + cc] + bp[cc];
                tb[rr2*HLD + cc] = wmma::__float_to_tf32(gelu_exact(v));
            }
        }
        __syncthreads();

        // GEMM2: acc2 += H[128,32] @ W2c[32,192]; 2x3 tile, B reused 2x
#pragma unroll
        for (int ks = 0; ks < 4; ks++){
            FragA fa0, fa1;
            wmma::load_matrix_sync(fa0, s_h + (2*rp  )*16*HLD + ks*8, HLD);
            wmma::load_matrix_sync(fa1, s_h + (2*rp+1)*16*HLD + ks*8, HLD);
#pragma unroll
            for (int j = 0; j < 3; j++){
                FragB fb; wmma::load_matrix_sync(fb, w2c + ks*8*W2LD + (3*cp + j)*16, W2LD);
                wmma::mma_sync(acc2[0][j], fa0, fb, acc2[0][j]);
                wmma::mma_sync(acc2[1][j], fa1, fb, acc2[1][j]);
            }
        }
        __syncthreads();                   // all reads of cur buffers + s_h done

        if (hc + 2 < 24){                  // restage cur buffer for chunk hc+2
            mlp_stage(w1, w2, (hc+2)*TH, w1c, w2c, t);
            cp_commit();
        }
    }

    // epilogue: acc2 -> s_xn (overwrite), then residual + bias, coalesced out
#pragma unroll
    for (int i = 0; i < 2; i++)
#pragma unroll
        for (int j = 0; j < 3; j++)
            wmma::store_matrix_sync(s_xn + (2*rp+i)*16*XLD + (3*cp+j)*16, acc2[i][j],
                                    XLD, wmma::mem_row_major);
    __syncthreads();

    float* ob = out + tok0 * DIMC;
    for (int idx = t; idx < TM*48; idx += ML_THREADS){
        int r = idx / 48, c4 = idx - r*48;
        float4 a  = *(float4*)(s_xn + r*XLD + c4*4);
        float4 xr = *(const float4*)(xb + (size_t)r*DIMC + c4*4);
        float4 bb = *(const float4*)(b2 + c4*4);
        a.x += xr.x + bb.x; a.y += xr.y + bb.y;
        a.z += xr.z + bb.z; a.w += xr.w + bb.w;
        *(float4*)(ob + (size_t)r*DIMC + c4*4) = a;
    }
}

// =====================================================================
// launch
// =====================================================================
extern "C" void kernel_launch(void* const* d_in, const int* in_sizes, int n_in,
                              void* d_out, int out_size)
{
    (void)in_sizes; (void)n_in; (void)out_size;
    const float* x      = (const float*)d_in[0];
    const float* qkv_w  = (const float*)d_in[1];
    const float* qkv_b  = (const float*)d_in[2];
    const float* proj_w = (const float*)d_in[3];
    const float* proj_b = (const float*)d_in[4];
    const float* g1     = (const float*)d_in[5];
    const float* be1    = (const float*)d_in[6];
    const float* g2     = (const float*)d_in[7];
    const float* be2    = (const float*)d_in[8];
    const float* w1     = (const float*)d_in[9];
    const float* b1     = (const float*)d_in[10];
    const float* w2     = (const float*)d_in[11];
    const float* b2     = (const float*)d_in[12];
    float* out = (float*)d_out;

    cudaFuncSetAttribute(attn_kernel, cudaFuncAttributeMaxDynamicSharedMemorySize, ATT_SMEM_BYTES);
    cudaFuncSetAttribute(mlp_kernel,  cudaFuncAttributeMaxDynamicSharedMemorySize, MLP_SMEM_BYTES);

    attn_kernel<<<NBLKS, AT_THREADS, ATT_SMEM_BYTES>>>(x, qkv_w, qkv_b, proj_w, proj_b, g1, be1);
    mlp_kernel<<<(BATCH*NTOK)/TM, ML_THREADS, MLP_SMEM_BYTES>>>(g2, be2, w1, b1, w2, b2, out);
}